// round 12
// baseline (speedup 1.0000x reference)
#include <cuda_runtime.h>
#include <cuda_bf16.h>
#include <stdint.h>
#include <math.h>
#include <float.h>

#define BB  2
#define CCH 64
#define NN  4096
#define KK  9
#define TT  2
#define CH2 128
#define CH4 256
#define M1  (BB*NN)          // 8192
#define MG  (BB*NN*KK)       // 73728

typedef unsigned long long ull;

// ---------------- scratch (per-branch double buffered) ----------------
__device__ float  d_x0[M1*CCH];
__device__ float  d_hpre[TT][M1*CCH];
__device__ float  d_h[TT][M1*CCH];
__device__ float  d_xn[TT][M1*CCH];
__device__ __nv_bfloat16 d_xnh[TT][M1*CCH];
__device__ __nv_bfloat16 d_xnl[TT][M1*CCH];
__device__ float  d_sqv[TT][M1];
__device__ int    d_idx[TT][M1*KK];
__device__ float  d_u[TT][M1*CH2];
__device__ float  d_v[TT][M1*CH2];
__device__ float  d_xmax[TT][M1*CH2];
__device__ float  d_xmin[TT][M1*CH2];
__device__ float  d_pre2[TT][M1*CCH];
__device__ float  d_res[TT][M1*CCH];
__device__ float  d_pref1[TT][(size_t)M1*CH4];
__device__ float  d_pref2[TT][M1*CCH];
__device__ double d_stats[10*512];

// ---------------- packed f32x2 helpers ----------------
__device__ __forceinline__ void ffma2(ull& d, ull a, ull b) {
    asm("fma.rn.f32x2 %0, %1, %2, %0;" : "+l"(d) : "l"(a), "l"(b));
}
__device__ __forceinline__ ull dup_f32(float x) {
    ull r; asm("mov.b64 %0, {%1, %1};" : "=l"(r) : "f"(x)); return r;
}
__device__ __forceinline__ float2 unpack2(ull v) {
    float2 r; asm("mov.b64 {%0, %1}, %2;" : "=f"(r.x), "=f"(r.y) : "l"(v)); return r;
}

__device__ __forceinline__ float gelu_exact(float x) {
    return 0.5f * x * (1.0f + erff(x * 0.70710678118654752f));
}

__device__ __forceinline__ void block_scale(const double* __restrict__ slot,
                                            const float* __restrict__ g,
                                            const float* __restrict__ bt,
                                            int Cc, int M,
                                            float* sSc, float* sSh)
{
    for (int c = threadIdx.x; c < Cc; c += blockDim.x) {
        double mean = slot[c] / (double)M;
        double var  = slot[Cc + c] / (double)M - mean*mean;
        float sc = g[c] * rsqrtf((float)var + 1e-5f);
        sSc[c] = sc;
        sSh[c] = bt[c] - (float)mean * sc;
    }
    __syncthreads();
}

__global__ void k_zero_stats_all() {
    for (int i = threadIdx.x; i < 10*512; i += blockDim.x) d_stats[i] = 0.0;
}

// ---------------- warp mma helpers ----------------
__device__ __forceinline__ uint32_t smem_u32(const void* p) {
    uint32_t a;
    asm("{ .reg .u64 t; cvta.to.shared.u64 t, %1; cvt.u32.u64 %0, t; }" : "=r"(a) : "l"(p));
    return a;
}
__device__ __forceinline__ void ldsm_x4(uint32_t& r0, uint32_t& r1, uint32_t& r2, uint32_t& r3,
                                        uint32_t addr) {
    asm volatile("ldmatrix.sync.aligned.m8n8.x4.shared.b16 {%0,%1,%2,%3}, [%4];"
                 : "=r"(r0), "=r"(r1), "=r"(r2), "=r"(r3) : "r"(addr));
}
__device__ __forceinline__ void ldsm_x2(uint32_t& r0, uint32_t& r1, uint32_t addr) {
    asm volatile("ldmatrix.sync.aligned.m8n8.x2.shared.b16 {%0,%1}, [%2];"
                 : "=r"(r0), "=r"(r1) : "r"(addr));
}
__device__ __forceinline__ void mma16816(float& d0, float& d1, float& d2, float& d3,
                                         const uint32_t* a, uint32_t b0, uint32_t b1) {
    asm volatile(
        "mma.sync.aligned.m16n8k16.row.col.f32.bf16.bf16.f32 "
        "{%0,%1,%2,%3}, {%4,%5,%6,%7}, {%8,%9}, {%0,%1,%2,%3};"
        : "+f"(d0), "+f"(d1), "+f"(d2), "+f"(d3)
        : "r"(a[0]), "r"(a[1]), "r"(a[2]), "r"(a[3]), "r"(b0), "r"(b1));
}

// ---------------- tiled transpose x (B,C,N) -> x0 (B,N,C) ----------------
__global__ __launch_bounds__(256) void k_transpose_in(const float* __restrict__ x,
                                                      float* __restrict__ x0) {
    __shared__ float tile[32][33];
    int b  = blockIdx.z;
    int n0 = blockIdx.x * 32, c0 = blockIdx.y * 32;
    int tx = threadIdx.x, ty = threadIdx.y;
#pragma unroll
    for (int i = ty; i < 32; i += 8)
        tile[i][tx] = x[((size_t)b*CCH + c0 + i)*NN + n0 + tx];
    __syncthreads();
#pragma unroll
    for (int i = ty; i < 32; i += 8)
        x0[((size_t)b*NN + n0 + i)*CCH + c0 + tx] = tile[tx][i];
}

// ---------------- GEMM BM=64 BN=64 BK=16, fused input/epilogue ----------------
template<int MODE>
__global__ __launch_bounds__(256) void k_gemm(
    const float* __restrict__ A, const float* __restrict__ aux,
    const float* __restrict__ W, const float* __restrict__ bias,
    float* __restrict__ C, double* __restrict__ slotOut,
    int Kd, int Nd,
    const double* __restrict__ slotIn, const float* __restrict__ gIn,
    const float* __restrict__ btIn, int Min, float* __restrict__ resOut)
{
    __shared__ __align__(16) float sA[16][68];
    __shared__ __align__(16) float sB[16][68];
    __shared__ float sScIn[256], sShIn[256];
    int tid = threadIdx.x;
    int tx = tid & 15, ty = tid >> 4;
    int row0 = blockIdx.y * 64;
    int col0 = blockIdx.x * 64;

    if (MODE != 0) {
        for (int c = tid; c < Kd; c += 256) {
            double mean = slotIn[c] / (double)Min;
            double var  = slotIn[Kd + c] / (double)Min - mean*mean;
            float sc = gIn[c] * rsqrtf((float)var + 1e-5f);
            sScIn[c] = sc;
            sShIn[c] = btIn[c] - (float)mean * sc;
        }
        __syncthreads();
    }

    ull accp[2][4];
#pragma unroll
    for (int i = 0; i < 2; i++)
#pragma unroll
        for (int j = 0; j < 4; j++) accp[i][j] = 0ULL;

    for (int k0 = 0; k0 < Kd; k0 += 16) {
        {
            int r  = tid >> 2;
            int kk = (tid & 3) * 4;
            size_t base = (size_t)(row0 + r)*Kd + k0 + kk;
            float vv[4];
            if (MODE == 0) {
                float4 v = *(const float4*)(A + base);
                vv[0]=v.x; vv[1]=v.y; vv[2]=v.z; vv[3]=v.w;
            } else if (MODE == 1) {
                float4 vx = *(const float4*)(A + base);
                float4 vn = *(const float4*)(aux + base);
                float ax[4] = {vx.x, vx.y, vx.z, vx.w};
                float an[4] = {vn.x, vn.y, vn.z, vn.w};
#pragma unroll
                for (int i = 0; i < 4; i++) {
                    float sc = sScIn[k0+kk+i], sh = sShIn[k0+kk+i];
                    vv[i] = fmaxf(gelu_exact(ax[i]*sc + sh), gelu_exact(an[i]*sc + sh));
                }
            } else if (MODE == 2) {
                float4 vp = *(const float4*)(A + base);
                float ap[4] = {vp.x, vp.y, vp.z, vp.w};
#pragma unroll
                for (int i = 0; i < 4; i++)
                    vv[i] = gelu_exact(ap[i]*sScIn[k0+kk+i] + sShIn[k0+kk+i]);
            } else {
                float4 vp = *(const float4*)(A + base);
                float4 vr = *(const float4*)(aux + base);
                float ap[4] = {vp.x, vp.y, vp.z, vp.w};
                float ar[4] = {vr.x, vr.y, vr.z, vr.w};
#pragma unroll
                for (int i = 0; i < 4; i++)
                    vv[i] = ap[i]*sScIn[k0+kk+i] + sShIn[k0+kk+i] + ar[i];
                if (blockIdx.x == 0)
                    *(float4*)(resOut + base) = make_float4(vv[0], vv[1], vv[2], vv[3]);
            }
#pragma unroll
            for (int i = 0; i < 4; i++) sA[kk+i][r] = vv[i];
        }
        {
            int r  = tid >> 4;
            int nn = (tid & 15) * 4;
            float4 v = *(const float4*)(W + (size_t)(k0 + r)*Nd + col0 + nn);
            sB[r][nn+0] = v.x; sB[r][nn+1] = v.y; sB[r][nn+2] = v.z; sB[r][nn+3] = v.w;
        }
        __syncthreads();
#pragma unroll
        for (int k = 0; k < 16; k++) {
            ulonglong2 ra = *(const ulonglong2*)&sA[k][ty*4];
            float4 rbf = *(const float4*)&sB[k][tx*4];
            ull rb0 = dup_f32(rbf.x), rb1 = dup_f32(rbf.y);
            ull rb2 = dup_f32(rbf.z), rb3 = dup_f32(rbf.w);
            ffma2(accp[0][0], ra.x, rb0); ffma2(accp[0][1], ra.x, rb1);
            ffma2(accp[0][2], ra.x, rb2); ffma2(accp[0][3], ra.x, rb3);
            ffma2(accp[1][0], ra.y, rb0); ffma2(accp[1][1], ra.y, rb1);
            ffma2(accp[1][2], ra.y, rb2); ffma2(accp[1][3], ra.y, rb3);
        }
        __syncthreads();
    }
    float acc[4][4];
#pragma unroll
    for (int ip = 0; ip < 2; ip++)
#pragma unroll
        for (int j = 0; j < 4; j++) {
            float2 u = unpack2(accp[ip][j]);
            acc[2*ip][j] = u.x; acc[2*ip+1][j] = u.y;
        }
    float bb[4];
#pragma unroll
    for (int j = 0; j < 4; j++) bb[j] = bias[col0 + tx*4 + j];
#pragma unroll
    for (int i = 0; i < 4; i++) {
#pragma unroll
        for (int j = 0; j < 4; j++) acc[i][j] += bb[j];
        *(float4*)(C + (size_t)(row0 + ty*4 + i)*Nd + col0 + tx*4) =
            make_float4(acc[i][0], acc[i][1], acc[i][2], acc[i][3]);
    }
    float s[4], s2[4];
#pragma unroll
    for (int j = 0; j < 4; j++) {
        s[j] = 0.f; s2[j] = 0.f;
#pragma unroll
        for (int i = 0; i < 4; i++) { float v = acc[i][j]; s[j] += v; s2[j] += v*v; }
    }
    float* sRed = &sA[0][0];
    __syncthreads();
#pragma unroll
    for (int j = 0; j < 4; j++) sRed[ty*64 + tx*4 + j] = s[j];
    __syncthreads();
    if (tid < 64) {
        float tot = 0.f;
#pragma unroll
        for (int yy = 0; yy < 16; yy++) tot += sRed[yy*64 + tid];
        atomicAdd(&slotOut[col0 + tid], (double)tot);
    }
    __syncthreads();
#pragma unroll
    for (int j = 0; j < 4; j++) sRed[ty*64 + tx*4 + j] = s2[j];
    __syncthreads();
    if (tid < 64) {
        float tot = 0.f;
#pragma unroll
        for (int yy = 0; yy < 16; yy++) tot += sRed[yy*64 + tid];
        atomicAdd(&slotOut[Nd + col0 + tid], (double)tot);
    }
}

// ---------------- u/v GEMM ----------------
__global__ __launch_bounds__(256) void k_uv(
    const float* __restrict__ h, const float* __restrict__ Wg,
    float* __restrict__ u, float* __restrict__ v)
{
    __shared__ __align__(16) float sA[16][132];
    __shared__ __align__(16) float sB[16][132];
    int zs = blockIdx.z;
    const float* W = Wg + (zs == 0 ? (size_t)CCH*CH2 : 0);
    float* C = (zs == 0) ? u : v;
    int tid = threadIdx.x;
    int tx = tid & 15, ty = tid >> 4;
    int r0 = blockIdx.y * 128;
    ull accp[4][8];
#pragma unroll
    for (int i = 0; i < 4; i++)
#pragma unroll
        for (int j = 0; j < 8; j++) accp[i][j] = 0ULL;

    for (int k0 = 0; k0 < CCH; k0 += 16) {
#pragma unroll
        for (int l = 0; l < 2; l++) {
            int e = tid + l*256;
            int rr = e >> 2;
            int kk = (e & 3) * 4;
            float4 vv = *(const float4*)(h + (size_t)(r0 + rr)*CCH + k0 + kk);
            sA[kk+0][rr] = vv.x; sA[kk+1][rr] = vv.y; sA[kk+2][rr] = vv.z; sA[kk+3][rr] = vv.w;
        }
#pragma unroll
        for (int l = 0; l < 2; l++) {
            int e = tid + l*256;
            int rr = e >> 5;
            int nn = (e & 31) * 4;
            float4 vv = *(const float4*)(W + (size_t)(k0 + rr)*CH2 + nn);
            sB[rr][nn+0] = vv.x; sB[rr][nn+1] = vv.y; sB[rr][nn+2] = vv.z; sB[rr][nn+3] = vv.w;
        }
        __syncthreads();
#pragma unroll
        for (int k = 0; k < 16; k++) {
            ulonglong2 ra01 = *(const ulonglong2*)&sA[k][ty*8];
            ulonglong2 ra23 = *(const ulonglong2*)&sA[k][ty*8 + 4];
            float rbf[8];
            *(float4*)&rbf[0] = *(const float4*)&sB[k][tx*8];
            *(float4*)&rbf[4] = *(const float4*)&sB[k][tx*8 + 4];
            ull rap[4] = {ra01.x, ra01.y, ra23.x, ra23.y};
            ull rb[8];
#pragma unroll
            for (int j = 0; j < 8; j++) rb[j] = dup_f32(rbf[j]);
#pragma unroll
            for (int ip = 0; ip < 4; ip++)
#pragma unroll
                for (int j = 0; j < 8; j++) ffma2(accp[ip][j], rap[ip], rb[j]);
        }
        __syncthreads();
    }
#pragma unroll
    for (int ip = 0; ip < 4; ip++) {
        float acc0[8], acc1[8];
#pragma unroll
        for (int j = 0; j < 8; j++) {
            float2 uu = unpack2(accp[ip][j]);
            acc0[j] = uu.x; acc1[j] = uu.y;
        }
        float* cp0 = C + (size_t)(r0 + ty*8 + 2*ip)*CH2 + tx*8;
        float* cp1 = C + (size_t)(r0 + ty*8 + 2*ip + 1)*CH2 + tx*8;
        *(float4*)cp0       = make_float4(acc0[0], acc0[1], acc0[2], acc0[3]);
        *(float4*)(cp0 + 4) = make_float4(acc0[4], acc0[5], acc0[6], acc0[7]);
        *(float4*)cp1       = make_float4(acc1[0], acc1[1], acc1[2], acc1[3]);
        *(float4*)(cp1 + 4) = make_float4(acc1[4], acc1[5], acc1[6], acc1[7]);
    }
}

// ---------------- gather ----------------
__global__ __launch_bounds__(256) void k_gather(
    const float* __restrict__ u, const float* __restrict__ v,
    const int* __restrict__ idx, const float* __restrict__ bias,
    float* __restrict__ xmax, float* __restrict__ xmin,
    double* __restrict__ slot)
{
    __shared__ int sRow[32*KK];
    __shared__ float sS[256];
    int tid = threadIdx.x;
    int c = tid & 127, half = tid >> 7;
    int bn0 = blockIdx.x * 32;
    for (int i = tid; i < 32*KK; i += 256) {
        int bn = bn0 + i/KK;
        int j = idx[(size_t)bn0*KK + i];
        sRow[i] = (bn & 4096) + j;
    }
    __syncthreads();
    float bias_c = bias[c];
    float s = 0.f, s2 = 0.f;
#pragma unroll 2
    for (int pass = 0; pass < 16; pass++) {
        int bnl = pass*2 + half;
        int bn = bn0 + bnl;
        float w_part = v[(size_t)bn*CH2 + c] - u[(size_t)bn*CH2 + c] + bias_c;
        float mx = -FLT_MAX, mn = FLT_MAX;
#pragma unroll
        for (int k = 0; k < KK; k++) {
            float uv = u[(size_t)sRow[bnl*KK + k]*CH2 + c];
            float val = w_part + uv;
            mx = fmaxf(mx, val); mn = fminf(mn, val);
            s += val; s2 += val*val;
        }
        xmax[(size_t)bn*CH2 + c] = mx;
        xmin[(size_t)bn*CH2 + c] = mn;
    }
    sS[tid] = s;
    __syncthreads();
    if (half == 0) atomicAdd(&slot[c], (double)(sS[c] + sS[c + 128]));
    __syncthreads();
    sS[tid] = s2;
    __syncthreads();
    if (half == 0) atomicAdd(&slot[CH2 + c], (double)(sS[c] + sS[c + 128]));
}

// ---------------- BN apply + rownorm + fp32 xn + bf16 hi/lo split ----------------
__global__ __launch_bounds__(256) void k_apply_norm(
    const float* __restrict__ pre, float* __restrict__ h,
    float* __restrict__ xn,
    __nv_bfloat16* __restrict__ xnh, __nv_bfloat16* __restrict__ xnl,
    float* __restrict__ sqv,
    const float* __restrict__ g, const float* __restrict__ bt,
    const double* __restrict__ slot)
{
    __shared__ float sSc[CCH], sSh[CCH];
    block_scale(slot, g, bt, CCH, M1, sSc, sSh);
    int wid = threadIdx.x >> 5, lane = threadIdx.x & 31;
    int r = blockIdx.x * 8 + wid;
    float2 v = ((const float2*)(pre + (size_t)r*CCH))[lane];
    float a  = v.x*sSc[lane*2]   + sSh[lane*2];
    float b2 = v.y*sSc[lane*2+1] + sSh[lane*2+1];
    ((float2*)(h + (size_t)r*CCH))[lane] = make_float2(a, b2);
    float ss = a*a + b2*b2;
#pragma unroll
    for (int o = 16; o > 0; o >>= 1) ss += __shfl_xor_sync(0xffffffff, ss, o);
    float inv = 1.0f / fmaxf(sqrtf(ss), 1e-12f);
    float x0v = a*inv, x1v = b2*inv;
    ((float2*)(xn + (size_t)r*CCH))[lane] = make_float2(x0v, x1v);
    __nv_bfloat16 h0 = __float2bfloat16(x0v);
    __nv_bfloat16 h1 = __float2bfloat16(x1v);
    __nv_bfloat16 l0 = __float2bfloat16(x0v - __bfloat162float(h0));
    __nv_bfloat16 l1 = __float2bfloat16(x1v - __bfloat162float(h1));
    __nv_bfloat162 ph; ph.x = h0; ph.y = h1;
    __nv_bfloat162 pl; pl.x = l0; pl.y = l1;
    ((__nv_bfloat162*)(xnh + (size_t)r*CCH))[lane] = ph;
    ((__nv_bfloat162*)(xnl + (size_t)r*CCH))[lane] = pl;
    if (lane == 0) sqv[r] = ss*inv*inv;
}

// ---------------- tensor-core KNN (128 q/block) + exact fp32 refine ----------------
// 8 warps = 8 query-groups of 16; each warp sweeps all 16 n8 j-blocks.
// smem: Ah 18432 | Al 18432 | Jh 18432 | Jl 18432 | sqj 512 = 74240 bytes.
// Merge overlay: mD[128][4][9]@0, mI@18432, cI[128][16]@36864, cD@45056.
#define KROW 144
#define NCAND 16
#define KNNT_SMEM 74240
__global__ __launch_bounds__(256) void k_knn_tc(
    const float* __restrict__ xn,
    const __nv_bfloat16* __restrict__ xh, const __nv_bfloat16* __restrict__ xl,
    const float* __restrict__ sqv, int* __restrict__ idxout)
{
    extern __shared__ char sm[];
    uint32_t sb = smem_u32(sm);
    const uint32_t oAh = 0, oAl = 18432, oJh = 36864, oJl = 55296;
    float* sqj = (float*)(sm + 73728);

    int tid = threadIdx.x, lane = tid & 31, wid = tid >> 5;
    int qg = wid;                        // 0..7
    int b = blockIdx.x >> 5, qt = blockIdx.x & 31;
    int qbase = qt * 128;
    size_t boff = (size_t)b * NN;

    // stage A (128 query rows, hi+lo)
#pragma unroll
    for (int l = 0; l < 4; l++) {
        int e = tid + l*256;
        int row = e >> 3, seg = e & 7;
        uint32_t doff = (uint32_t)row*KROW + (uint32_t)seg*16;
        size_t gidx = (boff + qbase + row)*CCH + seg*8;
        *(uint4*)(sm + oAh + doff) = *(const uint4*)(xh + gidx);
        *(uint4*)(sm + oAl + doff) = *(const uint4*)(xl + gidx);
    }
    __syncthreads();

    uint32_t afh[4][4], afl[4][4];
    {
        uint32_t arow = (uint32_t)(qg*16 + (lane & 7) + ((lane >> 3) & 1)*8);
        uint32_t acol = (uint32_t)(((lane >> 4) & 1)*16);
#pragma unroll
        for (int ks = 0; ks < 4; ks++) {
            uint32_t ad = sb + arow*KROW + acol + (uint32_t)ks*32;
            ldsm_x4(afh[ks][0], afh[ks][1], afh[ks][2], afh[ks][3], ad + oAh);
            ldsm_x4(afl[ks][0], afl[ks][1], afl[ks][2], afl[ks][3], ad + oAl);
        }
    }

    int g = lane >> 2, tg = lane & 3;
    int q0 = qg*16 + g;
    float sqi0 = sqv[boff + qbase + q0];
    float sqi1 = sqv[boff + qbase + q0 + 8];

    float bd[2][9]; int bi[2][9];
#pragma unroll
    for (int hh = 0; hh < 2; hh++)
#pragma unroll
        for (int k = 0; k < 9; k++) { bd[hh][k] = FLT_MAX; bi[hh][k] = 0x7fffffff; }

    uint32_t brow_in = (uint32_t)(lane & 7);
    uint32_t bcol = (uint32_t)(((lane >> 3) & 1)*16);

    for (int jt = 0; jt < 32; jt++) {
        __syncthreads();
#pragma unroll
        for (int l = 0; l < 4; l++) {
            int e = tid + l*256;
            int row = e >> 3, seg = e & 7;
            uint32_t doff = (uint32_t)row*KROW + (uint32_t)seg*16;
            size_t gidx = (boff + (size_t)jt*128 + row)*CCH + seg*8;
            *(uint4*)(sm + oJh + doff) = *(const uint4*)(xh + gidx);
            *(uint4*)(sm + oJl + doff) = *(const uint4*)(xl + gidx);
        }
        if (tid < 128) sqj[tid] = sqv[boff + (size_t)jt*128 + tid];
        __syncthreads();

#pragma unroll
        for (int nb = 0; nb < 16; nb++) {
            uint32_t badd = sb + ((uint32_t)(nb*8) + brow_in)*KROW + bcol;
            float d0 = 0.f, d1 = 0.f, d2 = 0.f, d3 = 0.f;
#pragma unroll
            for (int ks = 0; ks < 4; ks++) {
                uint32_t bh0, bh1, bl0, bl1;
                ldsm_x2(bh0, bh1, badd + oJh + (uint32_t)ks*32);
                ldsm_x2(bl0, bl1, badd + oJl + (uint32_t)ks*32);
                mma16816(d0, d1, d2, d3, afh[ks], bh0, bh1);
                mma16816(d0, d1, d2, d3, afl[ks], bh0, bh1);
                mma16816(d0, d1, d2, d3, afh[ks], bl0, bl1);
            }
            int jl = nb*8 + tg*2;
            int jg = jt*128 + jl;
            float sq0 = sqj[jl], sq1 = sqj[jl + 1];
#pragma unroll
            for (int e4 = 0; e4 < 4; e4++) {
                int hh = e4 >> 1;
                float dot = (e4 == 0) ? d0 : (e4 == 1) ? d1 : (e4 == 2) ? d2 : d3;
                float sqa = (hh == 0) ? sqi0 : sqi1;
                float sqb = (e4 & 1) ? sq1 : sq0;
                int jidx = jg + (e4 & 1);
                float dist = fmaf(-2.0f, dot, sqa + sqb);
                if (dist < bd[hh][8]) {
                    float dc = dist; int ic = jidx;
#pragma unroll
                    for (int k = 0; k < 9; k++) {
                        if (dc < bd[hh][k]) {
                            float td = bd[hh][k]; int ti = bi[hh][k];
                            bd[hh][k] = dc; bi[hh][k] = ic; dc = td; ic = ti;
                        }
                    }
                }
            }
        }
    }

    // merge 4 partitions -> top-NCAND approx candidates, then exact refine
    __syncthreads();
    float* mD = (float*)sm;                        // [128][4][9]
    int*   mI = (int*)(sm + 18432);                // [128][4][9]
    int*   cI = (int*)(sm + 36864);                // [128][NCAND]
    float* cD = (float*)(sm + 45056);              // [128][NCAND]
    int p = tg;
#pragma unroll
    for (int k = 0; k < 9; k++) {
        mD[(q0*4 + p)*9 + k]       = bd[0][k];
        mI[(q0*4 + p)*9 + k]       = bi[0][k];
        mD[((q0+8)*4 + p)*9 + k]   = bd[1][k];
        mI[((q0+8)*4 + p)*9 + k]   = bi[1][k];
    }
    __syncthreads();
    if (tid < 128) {
        int q = tid;
        int ptr[4];
#pragma unroll
        for (int pp = 0; pp < 4; pp++) ptr[pp] = 0;
        for (int k = 0; k < NCAND; k++) {
            float bestd = FLT_MAX; int besti = 0x7fffffff; int bp = 0;
#pragma unroll
            for (int pp = 0; pp < 4; pp++) {
                int hh = ptr[pp];
                if (hh < 9) {
                    float dc = mD[(q*4 + pp)*9 + hh];
                    int   ic = mI[(q*4 + pp)*9 + hh];
                    if (dc < bestd || (dc == bestd && ic < besti)) {
                        bestd = dc; besti = ic; bp = pp;
                    }
                }
            }
            cI[q*NCAND + k] = besti;
            ptr[bp]++;
        }
    }
    __syncthreads();
    // exact fp32 distances: 2 threads per query, 8 candidates each
    {
        int q = tid >> 1, sub = tid & 1;
        const float* xq = xn + (boff + qbase + q)*CCH;
        float sqq = sqv[boff + qbase + q];
#pragma unroll
        for (int cc = 0; cc < 8; cc++) {
            int slot = sub*8 + cc;
            int cand = cI[q*NCAND + slot];
            const float* xj = xn + (boff + cand)*CCH;
            float a0=0.f, a1=0.f, a2=0.f, a3=0.f;
#pragma unroll
            for (int c4 = 0; c4 < 16; c4++) {
                float4 qv = *(const float4*)(xq + c4*4);
                float4 jv = *(const float4*)(xj + c4*4);
                a0 += qv.x*jv.x; a1 += qv.y*jv.y; a2 += qv.z*jv.z; a3 += qv.w*jv.w;
            }
            float dot = (a0+a1) + (a2+a3);
            cD[q*NCAND + slot] = sqq - 2.0f*dot + sqv[boff + cand];
        }
    }
    __syncthreads();
    if (tid < 128) {
        int q = tid;
        float dl[NCAND]; int il[NCAND];
#pragma unroll
        for (int k = 0; k < NCAND; k++) { dl[k] = cD[q*NCAND + k]; il[k] = cI[q*NCAND + k]; }
#pragma unroll
        for (int k = 1; k < NCAND; k++) {
            float dk = dl[k]; int ik = il[k];
            int m = k;
#pragma unroll
            for (int jj = NCAND - 1; jj >= 1; jj--) {
                if (jj <= k) {
                    bool sm2 = (dk < dl[jj-1]) || (dk == dl[jj-1] && ik < il[jj-1]);
                    if (sm2) { dl[jj] = dl[jj-1]; il[jj] = il[jj-1]; m = jj - 1; }
                    else break;
                }
            }
            dl[m] = dk; il[m] = ik;
        }
        int* outI = idxout + (boff + qbase + q)*KK;
#pragma unroll
        for (int k = 0; k < KK; k++) outI[k] = il[k];
    }
}

// ---------------- final: BN(pref2)+res per branch, alpha mix, transpose ----------------
__global__ __launch_bounds__(256) void k_final(
    const float* __restrict__ alpha,
    const float* __restrict__ pref2, const float* __restrict__ res,
    const float* __restrict__ gf2, const float* __restrict__ btf2,
    const double* __restrict__ stats,
    float* __restrict__ out)
{
    __shared__ float sSc[2][CCH], sSh[2][CCH];
    __shared__ float t0[32][33], t1[32][33];
    int tx = threadIdx.x, ty = threadIdx.y;
    int tid = ty*32 + tx;
    for (int i = tid; i < 2*CCH; i += 256) {
        int t = i >> 6, c = i & 63;
        const double* slot = stats + (t*5 + 4)*512;
        double mean = slot[c] / (double)M1;
        double var  = slot[CCH + c] / (double)M1 - mean*mean;
        float sc = gf2[t*CCH + c] * rsqrtf((float)var + 1e-5f);
        sSc[t][c] = sc;
        sSh[t][c] = btf2[t*CCH + c] - (float)mean * sc;
    }
    __syncthreads();
    int b  = blockIdx.z;
    int n0 = blockIdx.x * 32, c0 = blockIdx.y * 32;
#pragma unroll
    for (int i = ty; i < 32; i += 8) {
        size_t e0 = ((size_t)b*NN + n0 + i)*CCH + c0 + tx;
        size_t e1 = (size_t)M1*CCH + e0;
        int c = c0 + tx;
        t0[i][tx] = pref2[e0]*sSc[0][c] + sSh[0][c] + res[e0];
        t1[i][tx] = pref2[e1]*sSc[1][c] + sSh[1][c] + res[e1];
    }
    __syncthreads();
    float a00 = alpha[0], a01 = alpha[1], a10 = alpha[2], a11 = alpha[3];
#pragma unroll
    for (int i = ty; i < 32; i += 8) {
        float f0 = t0[tx][i], f1 = t1[tx][i];
        out[(((size_t)0*BB + b)*CCH + c0 + i)*NN + n0 + tx] = a00*f0 + a01*f1;
        out[(((size_t)1*BB + b)*CCH + c0 + i)*NN + n0 + tx] = a10*f0 + a11*f1;
    }
}

// ---------------- host ----------------
struct BranchPtrs {
    float *hpre, *h, *xn, *sqv, *u, *v, *xmax, *xmin, *pre2, *res, *pref1, *pref2;
    __nv_bfloat16 *xnh, *xnl;
    int *idx;
};

extern "C" void kernel_launch(void* const* d_in, const int* in_sizes, int n_in,
                              void* d_out, int out_size) {
    (void)in_sizes; (void)n_in; (void)out_size;
    const float* x    = (const float*)d_in[0];
    const float* W1   = (const float*)d_in[1];
    const float* b1   = (const float*)d_in[2];
    const float* g1   = (const float*)d_in[3];
    const float* bt1  = (const float*)d_in[4];
    const float* Wg   = (const float*)d_in[5];
    const float* bg   = (const float*)d_in[6];
    const float* gg   = (const float*)d_in[7];
    const float* btg  = (const float*)d_in[8];
    const float* W2   = (const float*)d_in[9];
    const float* b2   = (const float*)d_in[10];
    const float* g2   = (const float*)d_in[11];
    const float* bt2  = (const float*)d_in[12];
    const float* Wf1  = (const float*)d_in[13];
    const float* bf1  = (const float*)d_in[14];
    const float* gf1  = (const float*)d_in[15];
    const float* btf1 = (const float*)d_in[16];
    const float* Wf2  = (const float*)d_in[17];
    const float* bf2  = (const float*)d_in[18];
    const float* gf2  = (const float*)d_in[19];
    const float* btf2 = (const float*)d_in[20];
    const float* alpha= (const float*)d_in[21];
    float* out = (float*)d_out;

    static cudaStream_t s1 = nullptr, sU[TT] = {nullptr, nullptr};
    static cudaEvent_t evF = nullptr, evJ = nullptr;
    static cudaEvent_t evA[TT] = {nullptr, nullptr}, evB[TT] = {nullptr, nullptr};
    static bool attrSet = false;
    if (!s1) {
        cudaStreamCreateWithFlags(&s1, cudaStreamNonBlocking);
        cudaStreamCreateWithFlags(&sU[0], cudaStreamNonBlocking);
        cudaStreamCreateWithFlags(&sU[1], cudaStreamNonBlocking);
        cudaEventCreateWithFlags(&evF, cudaEventDisableTiming);
        cudaEventCreateWithFlags(&evJ, cudaEventDisableTiming);
        for (int t = 0; t < TT; t++) {
            cudaEventCreateWithFlags(&evA[t], cudaEventDisableTiming);
            cudaEventCreateWithFlags(&evB[t], cudaEventDisableTiming);
        }
    }
    if (!attrSet) {
        cudaFuncSetAttribute(k_knn_tc, cudaFuncAttributeMaxDynamicSharedMemorySize, KNNT_SMEM);
        attrSet = true;
    }

    float *p_x0;
    double* p_stats;
    cudaGetSymbolAddress((void**)&p_x0, d_x0);
    cudaGetSymbolAddress((void**)&p_stats, d_stats);

    BranchPtrs bp[TT];
    {
        float *base;
        cudaGetSymbolAddress((void**)&base, d_hpre);
        for (int t = 0; t < TT; t++) bp[t].hpre = base + (size_t)t*M1*CCH;
        cudaGetSymbolAddress((void**)&base, d_h);
        for (int t = 0; t < TT; t++) bp[t].h = base + (size_t)t*M1*CCH;
        cudaGetSymbolAddress((void**)&base, d_xn);
        for (int t = 0; t < TT; t++) bp[t].xn = base + (size_t)t*M1*CCH;
        cudaGetSymbolAddress((void**)&base, d_sqv);
        for (int t = 0; t < TT; t++) bp[t].sqv = base + (size_t)t*M1;
        cudaGetSymbolAddress((void**)&base, d_u);
        for (int t = 0; t < TT; t++) bp[t].u = base + (size_t)t*M1*CH2;
        cudaGetSymbolAddress((void**)&base, d_v);
        for (int t = 0; t < TT; t++) bp[t].v = base + (size_t)t*M1*CH2;
        cudaGetSymbolAddress((void**)&base, d_xmax);
        for (int t = 0; t < TT; t++) bp[t].xmax = base + (size_t)t*M1*CH2;
        cudaGetSymbolAddress((void**)&base, d_xmin);
        for (int t = 0; t < TT; t++) bp[t].xmin = base + (size_t)t*M1*CH2;
        cudaGetSymbolAddress((void**)&base, d_pre2);
        for (int t = 0; t < TT; t++) bp[t].pre2 = base + (size_t)t*M1*CCH;
        cudaGetSymbolAddress((void**)&base, d_res);
        for (int t = 0; t < TT; t++) bp[t].res = base + (size_t)t*M1*CCH;
        cudaGetSymbolAddress((void**)&base, d_pref1);
        for (int t = 0; t < TT; t++) bp[t].pref1 = base + (size_t)t*M1*CH4;
        cudaGetSymbolAddress((void**)&base, d_pref2);
        for (int t = 0; t < TT; t++) bp[t].pref2 = base + (size_t)t*M1*CCH;
        __nv_bfloat16* hb;
        cudaGetSymbolAddress((void**)&hb, d_xnh);
        for (int t = 0; t < TT; t++) bp[t].xnh = hb + (size_t)t*M1*CCH;
        cudaGetSymbolAddress((void**)&hb, d_xnl);
        for (int t = 0; t < TT; t++) bp[t].xnl = hb + (size_t)t*M1*CCH;
        int* ibase;
        cudaGetSymbolAddress((void**)&ibase, d_idx);
        for (int t = 0; t < TT; t++) bp[t].idx = ibase + (size_t)t*M1*KK;
    }

    k_zero_stats_all<<<1, 512>>>();
    k_transpose_in<<<dim3(NN/32, CCH/32, BB), dim3(32, 8)>>>(x, p_x0);

    cudaEventRecord(evF, 0);
    cudaStreamWaitEvent(s1, evF, 0);

    for (int t = 0; t < TT; t++) {
        cudaStream_t st = (t == 0) ? (cudaStream_t)0 : s1;
        BranchPtrs& p = bp[t];
        double* s_bn1  = p_stats + (t*5 + 0)*512;
        double* s_bng  = p_stats + (t*5 + 1)*512;
        double* s_bn2  = p_stats + (t*5 + 2)*512;
        double* s_bnf1 = p_stats + (t*5 + 3)*512;
        double* s_bnf2 = p_stats + (t*5 + 4)*512;

        k_gemm<0><<<dim3(1, M1/64), 256, 0, st>>>(
            p_x0, nullptr, W1 + (size_t)t*CCH*CCH, b1 + t*CCH,
            p.hpre, s_bn1, CCH, CCH, nullptr, nullptr, nullptr, 1, nullptr);
        k_apply_norm<<<M1/8, 256, 0, st>>>(p.hpre, p.h, p.xn, p.xnh, p.xnl, p.sqv,
                                           g1 + t*CCH, bt1 + t*CCH, s_bn1);
        // fork: uv on sU[t] (needs h), knn on st (needs xn)
        cudaEventRecord(evA[t], st);
        cudaStreamWaitEvent(sU[t], evA[t], 0);
        k_uv<<<dim3(1, M1/128, 2), 256, 0, sU[t]>>>(p.h, Wg + (size_t)t*CH2*CH2, p.u, p.v);
        cudaEventRecord(evB[t], sU[t]);
        k_knn_tc<<<BB*(NN/128), 256, KNNT_SMEM, st>>>(p.xn, p.xnh, p.xnl, p.sqv, p.idx);
        cudaStreamWaitEvent(st, evB[t], 0);
        // join: gather needs u, v, idx
        k_gather<<<M1/32, 256, 0, st>>>(p.u, p.v, p.idx, bg + t*CH2,
                                        p.xmax, p.xmin, s_bng);
        k_gemm<1><<<dim3(1, M1/64), 256, 0, st>>>(
            p.xmax, p.xmin, W2 + (size_t)t*CH2*CCH, b2 + t*CCH,
            p.pre2, s_bn2, CH2, CCH, s_bng, gg + t*CH2, btg + t*CH2, MG, nullptr);
        k_gemm<3><<<dim3(CH4/64, M1/64), 256, 0, st>>>(
            p.pre2, p_x0, Wf1 + (size_t)t*CCH*CH4, bf1 + t*CH4,
            p.pref1, s_bnf1, CCH, CH4, s_bn2, g2 + t*CCH, bt2 + t*CCH, M1, p.res);
        k_gemm<2><<<dim3(1, M1/64), 256, 0, st>>>(
            p.pref1, nullptr, Wf2 + (size_t)t*CH4*CCH, bf2 + t*CCH,
            p.pref2, s_bnf2, CH4, CCH, s_bnf1, gf1 + t*CH4, btf1 + t*CH4, M1, nullptr);
    }

    cudaEventRecord(evJ, s1);
    cudaStreamWaitEvent(0, evJ, 0);

    k_final<<<dim3(NN/32, CCH/32, BB), dim3(32, 8)>>>(alpha, bp[0].pref2, bp[0].res,
                                                      gf2, btf2, p_stats, out);
}

// round 14
// speedup vs baseline: 1.5369x; 1.5369x over previous
#include <cuda_runtime.h>
#include <cuda_bf16.h>
#include <stdint.h>
#include <math.h>
#include <float.h>

#define BB  2
#define CCH 64
#define NN  4096
#define KK  9
#define TT  2
#define CH2 128
#define CH4 256
#define M1  (BB*NN)          // 8192
#define MG  (BB*NN*KK)       // 73728

typedef unsigned long long ull;

// ---------------- scratch (per-branch double buffered) ----------------
__device__ float  d_x0[M1*CCH];
__device__ float  d_hpre[TT][M1*CCH];
__device__ float  d_h[TT][M1*CCH];
__device__ float  d_xn[TT][M1*CCH];
__device__ __nv_bfloat16 d_xnh[TT][M1*CCH];
__device__ __nv_bfloat16 d_xnl[TT][M1*CCH];
__device__ float  d_sqv[TT][M1];
__device__ int    d_idx[TT][M1*KK];
__device__ float  d_u[TT][M1*CH2];
__device__ float  d_v[TT][M1*CH2];
__device__ float  d_xmax[TT][M1*CH2];
__device__ float  d_xmin[TT][M1*CH2];
__device__ float  d_pre2[TT][M1*CCH];
__device__ float  d_res[TT][M1*CCH];
__device__ float  d_pref1[TT][(size_t)M1*CH4];
__device__ float  d_pref2[TT][M1*CCH];
__device__ double d_stats[10*512];

// ---------------- packed f32x2 helpers ----------------
__device__ __forceinline__ void ffma2(ull& d, ull a, ull b) {
    asm("fma.rn.f32x2 %0, %1, %2, %0;" : "+l"(d) : "l"(a), "l"(b));
}
__device__ __forceinline__ ull dup_f32(float x) {
    ull r; asm("mov.b64 %0, {%1, %1};" : "=l"(r) : "f"(x)); return r;
}
__device__ __forceinline__ float2 unpack2(ull v) {
    float2 r; asm("mov.b64 {%0, %1}, %2;" : "=f"(r.x), "=f"(r.y) : "l"(v)); return r;
}

__device__ __forceinline__ float gelu_exact(float x) {
    return 0.5f * x * (1.0f + erff(x * 0.70710678118654752f));
}

__device__ __forceinline__ void block_scale(const double* __restrict__ slot,
                                            const float* __restrict__ g,
                                            const float* __restrict__ bt,
                                            int Cc, int M,
                                            float* sSc, float* sSh)
{
    for (int c = threadIdx.x; c < Cc; c += blockDim.x) {
        double mean = slot[c] / (double)M;
        double var  = slot[Cc + c] / (double)M - mean*mean;
        float sc = g[c] * rsqrtf((float)var + 1e-5f);
        sSc[c] = sc;
        sSh[c] = bt[c] - (float)mean * sc;
    }
    __syncthreads();
}

__global__ void k_zero_stats_all() {
    for (int i = threadIdx.x; i < 10*512; i += blockDim.x) d_stats[i] = 0.0;
}

// ---------------- warp mma helpers ----------------
__device__ __forceinline__ uint32_t smem_u32(const void* p) {
    uint32_t a;
    asm("{ .reg .u64 t; cvta.to.shared.u64 t, %1; cvt.u32.u64 %0, t; }" : "=r"(a) : "l"(p));
    return a;
}
__device__ __forceinline__ void ldsm_x4(uint32_t& r0, uint32_t& r1, uint32_t& r2, uint32_t& r3,
                                        uint32_t addr) {
    asm volatile("ldmatrix.sync.aligned.m8n8.x4.shared.b16 {%0,%1,%2,%3}, [%4];"
                 : "=r"(r0), "=r"(r1), "=r"(r2), "=r"(r3) : "r"(addr));
}
__device__ __forceinline__ void ldsm_x2(uint32_t& r0, uint32_t& r1, uint32_t addr) {
    asm volatile("ldmatrix.sync.aligned.m8n8.x2.shared.b16 {%0,%1}, [%2];"
                 : "=r"(r0), "=r"(r1) : "r"(addr));
}
__device__ __forceinline__ void mma16816(float& d0, float& d1, float& d2, float& d3,
                                         const uint32_t* a, uint32_t b0, uint32_t b1) {
    asm volatile(
        "mma.sync.aligned.m16n8k16.row.col.f32.bf16.bf16.f32 "
        "{%0,%1,%2,%3}, {%4,%5,%6,%7}, {%8,%9}, {%0,%1,%2,%3};"
        : "+f"(d0), "+f"(d1), "+f"(d2), "+f"(d3)
        : "r"(a[0]), "r"(a[1]), "r"(a[2]), "r"(a[3]), "r"(b0), "r"(b1));
}

// ---------------- tiled transpose x (B,C,N) -> x0 (B,N,C) ----------------
__global__ __launch_bounds__(256) void k_transpose_in(const float* __restrict__ x,
                                                      float* __restrict__ x0) {
    __shared__ float tile[32][33];
    int b  = blockIdx.z;
    int n0 = blockIdx.x * 32, c0 = blockIdx.y * 32;
    int tx = threadIdx.x, ty = threadIdx.y;
#pragma unroll
    for (int i = ty; i < 32; i += 8)
        tile[i][tx] = x[((size_t)b*CCH + c0 + i)*NN + n0 + tx];
    __syncthreads();
#pragma unroll
    for (int i = ty; i < 32; i += 8)
        x0[((size_t)b*NN + n0 + i)*CCH + c0 + tx] = tile[tx][i];
}

// ---------------- GEMM BM=64 BN=64 BK=16, fused input/epilogue ----------------
template<int MODE>
__global__ __launch_bounds__(256) void k_gemm(
    const float* __restrict__ A, const float* __restrict__ aux,
    const float* __restrict__ W, const float* __restrict__ bias,
    float* __restrict__ C, double* __restrict__ slotOut,
    int Kd, int Nd,
    const double* __restrict__ slotIn, const float* __restrict__ gIn,
    const float* __restrict__ btIn, int Min, float* __restrict__ resOut)
{
    __shared__ __align__(16) float sA[16][68];
    __shared__ __align__(16) float sB[16][68];
    __shared__ float sScIn[256], sShIn[256];
    int tid = threadIdx.x;
    int tx = tid & 15, ty = tid >> 4;
    int row0 = blockIdx.y * 64;
    int col0 = blockIdx.x * 64;

    if (MODE != 0) {
        for (int c = tid; c < Kd; c += 256) {
            double mean = slotIn[c] / (double)Min;
            double var  = slotIn[Kd + c] / (double)Min - mean*mean;
            float sc = gIn[c] * rsqrtf((float)var + 1e-5f);
            sScIn[c] = sc;
            sShIn[c] = btIn[c] - (float)mean * sc;
        }
        __syncthreads();
    }

    ull accp[2][4];
#pragma unroll
    for (int i = 0; i < 2; i++)
#pragma unroll
        for (int j = 0; j < 4; j++) accp[i][j] = 0ULL;

    for (int k0 = 0; k0 < Kd; k0 += 16) {
        {
            int r  = tid >> 2;
            int kk = (tid & 3) * 4;
            size_t base = (size_t)(row0 + r)*Kd + k0 + kk;
            float vv[4];
            if (MODE == 0) {
                float4 v = *(const float4*)(A + base);
                vv[0]=v.x; vv[1]=v.y; vv[2]=v.z; vv[3]=v.w;
            } else if (MODE == 1) {
                float4 vx = *(const float4*)(A + base);
                float4 vn = *(const float4*)(aux + base);
                float ax[4] = {vx.x, vx.y, vx.z, vx.w};
                float an[4] = {vn.x, vn.y, vn.z, vn.w};
#pragma unroll
                for (int i = 0; i < 4; i++) {
                    float sc = sScIn[k0+kk+i], sh = sShIn[k0+kk+i];
                    vv[i] = fmaxf(gelu_exact(ax[i]*sc + sh), gelu_exact(an[i]*sc + sh));
                }
            } else if (MODE == 2) {
                float4 vp = *(const float4*)(A + base);
                float ap[4] = {vp.x, vp.y, vp.z, vp.w};
#pragma unroll
                for (int i = 0; i < 4; i++)
                    vv[i] = gelu_exact(ap[i]*sScIn[k0+kk+i] + sShIn[k0+kk+i]);
            } else {
                float4 vp = *(const float4*)(A + base);
                float4 vr = *(const float4*)(aux + base);
                float ap[4] = {vp.x, vp.y, vp.z, vp.w};
                float ar[4] = {vr.x, vr.y, vr.z, vr.w};
#pragma unroll
                for (int i = 0; i < 4; i++)
                    vv[i] = ap[i]*sScIn[k0+kk+i] + sShIn[k0+kk+i] + ar[i];
                if (blockIdx.x == 0)
                    *(float4*)(resOut + base) = make_float4(vv[0], vv[1], vv[2], vv[3]);
            }
#pragma unroll
            for (int i = 0; i < 4; i++) sA[kk+i][r] = vv[i];
        }
        {
            int r  = tid >> 4;
            int nn = (tid & 15) * 4;
            float4 v = *(const float4*)(W + (size_t)(k0 + r)*Nd + col0 + nn);
            sB[r][nn+0] = v.x; sB[r][nn+1] = v.y; sB[r][nn+2] = v.z; sB[r][nn+3] = v.w;
        }
        __syncthreads();
#pragma unroll
        for (int k = 0; k < 16; k++) {
            ulonglong2 ra = *(const ulonglong2*)&sA[k][ty*4];
            float4 rbf = *(const float4*)&sB[k][tx*4];
            ull rb0 = dup_f32(rbf.x), rb1 = dup_f32(rbf.y);
            ull rb2 = dup_f32(rbf.z), rb3 = dup_f32(rbf.w);
            ffma2(accp[0][0], ra.x, rb0); ffma2(accp[0][1], ra.x, rb1);
            ffma2(accp[0][2], ra.x, rb2); ffma2(accp[0][3], ra.x, rb3);
            ffma2(accp[1][0], ra.y, rb0); ffma2(accp[1][1], ra.y, rb1);
            ffma2(accp[1][2], ra.y, rb2); ffma2(accp[1][3], ra.y, rb3);
        }
        __syncthreads();
    }
    float acc[4][4];
#pragma unroll
    for (int ip = 0; ip < 2; ip++)
#pragma unroll
        for (int j = 0; j < 4; j++) {
            float2 u = unpack2(accp[ip][j]);
            acc[2*ip][j] = u.x; acc[2*ip+1][j] = u.y;
        }
    float bb[4];
#pragma unroll
    for (int j = 0; j < 4; j++) bb[j] = bias[col0 + tx*4 + j];
#pragma unroll
    for (int i = 0; i < 4; i++) {
#pragma unroll
        for (int j = 0; j < 4; j++) acc[i][j] += bb[j];
        *(float4*)(C + (size_t)(row0 + ty*4 + i)*Nd + col0 + tx*4) =
            make_float4(acc[i][0], acc[i][1], acc[i][2], acc[i][3]);
    }
    float s[4], s2[4];
#pragma unroll
    for (int j = 0; j < 4; j++) {
        s[j] = 0.f; s2[j] = 0.f;
#pragma unroll
        for (int i = 0; i < 4; i++) { float v = acc[i][j]; s[j] += v; s2[j] += v*v; }
    }
    float* sRed = &sA[0][0];
    __syncthreads();
#pragma unroll
    for (int j = 0; j < 4; j++) sRed[ty*64 + tx*4 + j] = s[j];
    __syncthreads();
    if (tid < 64) {
        float tot = 0.f;
#pragma unroll
        for (int yy = 0; yy < 16; yy++) tot += sRed[yy*64 + tid];
        atomicAdd(&slotOut[col0 + tid], (double)tot);
    }
    __syncthreads();
#pragma unroll
    for (int j = 0; j < 4; j++) sRed[ty*64 + tx*4 + j] = s2[j];
    __syncthreads();
    if (tid < 64) {
        float tot = 0.f;
#pragma unroll
        for (int yy = 0; yy < 16; yy++) tot += sRed[yy*64 + tid];
        atomicAdd(&slotOut[Nd + col0 + tid], (double)tot);
    }
}

// ---------------- u/v GEMM ----------------
__global__ __launch_bounds__(256) void k_uv(
    const float* __restrict__ h, const float* __restrict__ Wg,
    float* __restrict__ u, float* __restrict__ v)
{
    __shared__ __align__(16) float sA[16][132];
    __shared__ __align__(16) float sB[16][132];
    int zs = blockIdx.z;
    const float* W = Wg + (zs == 0 ? (size_t)CCH*CH2 : 0);
    float* C = (zs == 0) ? u : v;
    int tid = threadIdx.x;
    int tx = tid & 15, ty = tid >> 4;
    int r0 = blockIdx.y * 128;
    ull accp[4][8];
#pragma unroll
    for (int i = 0; i < 4; i++)
#pragma unroll
        for (int j = 0; j < 8; j++) accp[i][j] = 0ULL;

    for (int k0 = 0; k0 < CCH; k0 += 16) {
#pragma unroll
        for (int l = 0; l < 2; l++) {
            int e = tid + l*256;
            int rr = e >> 2;
            int kk = (e & 3) * 4;
            float4 vv = *(const float4*)(h + (size_t)(r0 + rr)*CCH + k0 + kk);
            sA[kk+0][rr] = vv.x; sA[kk+1][rr] = vv.y; sA[kk+2][rr] = vv.z; sA[kk+3][rr] = vv.w;
        }
#pragma unroll
        for (int l = 0; l < 2; l++) {
            int e = tid + l*256;
            int rr = e >> 5;
            int nn = (e & 31) * 4;
            float4 vv = *(const float4*)(W + (size_t)(k0 + rr)*CH2 + nn);
            sB[rr][nn+0] = vv.x; sB[rr][nn+1] = vv.y; sB[rr][nn+2] = vv.z; sB[rr][nn+3] = vv.w;
        }
        __syncthreads();
#pragma unroll
        for (int k = 0; k < 16; k++) {
            ulonglong2 ra01 = *(const ulonglong2*)&sA[k][ty*8];
            ulonglong2 ra23 = *(const ulonglong2*)&sA[k][ty*8 + 4];
            float rbf[8];
            *(float4*)&rbf[0] = *(const float4*)&sB[k][tx*8];
            *(float4*)&rbf[4] = *(const float4*)&sB[k][tx*8 + 4];
            ull rap[4] = {ra01.x, ra01.y, ra23.x, ra23.y};
            ull rb[8];
#pragma unroll
            for (int j = 0; j < 8; j++) rb[j] = dup_f32(rbf[j]);
#pragma unroll
            for (int ip = 0; ip < 4; ip++)
#pragma unroll
                for (int j = 0; j < 8; j++) ffma2(accp[ip][j], rap[ip], rb[j]);
        }
        __syncthreads();
    }
#pragma unroll
    for (int ip = 0; ip < 4; ip++) {
        float acc0[8], acc1[8];
#pragma unroll
        for (int j = 0; j < 8; j++) {
            float2 uu = unpack2(accp[ip][j]);
            acc0[j] = uu.x; acc1[j] = uu.y;
        }
        float* cp0 = C + (size_t)(r0 + ty*8 + 2*ip)*CH2 + tx*8;
        float* cp1 = C + (size_t)(r0 + ty*8 + 2*ip + 1)*CH2 + tx*8;
        *(float4*)cp0       = make_float4(acc0[0], acc0[1], acc0[2], acc0[3]);
        *(float4*)(cp0 + 4) = make_float4(acc0[4], acc0[5], acc0[6], acc0[7]);
        *(float4*)cp1       = make_float4(acc1[0], acc1[1], acc1[2], acc1[3]);
        *(float4*)(cp1 + 4) = make_float4(acc1[4], acc1[5], acc1[6], acc1[7]);
    }
}

// ---------------- gather ----------------
__global__ __launch_bounds__(256) void k_gather(
    const float* __restrict__ u, const float* __restrict__ v,
    const int* __restrict__ idx, const float* __restrict__ bias,
    float* __restrict__ xmax, float* __restrict__ xmin,
    double* __restrict__ slot)
{
    __shared__ int sRow[32*KK];
    __shared__ float sS[256];
    int tid = threadIdx.x;
    int c = tid & 127, half = tid >> 7;
    int bn0 = blockIdx.x * 32;
    for (int i = tid; i < 32*KK; i += 256) {
        int bn = bn0 + i/KK;
        int j = idx[(size_t)bn0*KK + i];
        sRow[i] = (bn & 4096) + j;
    }
    __syncthreads();
    float bias_c = bias[c];
    float s = 0.f, s2 = 0.f;
#pragma unroll 2
    for (int pass = 0; pass < 16; pass++) {
        int bnl = pass*2 + half;
        int bn = bn0 + bnl;
        float w_part = v[(size_t)bn*CH2 + c] - u[(size_t)bn*CH2 + c] + bias_c;
        float mx = -FLT_MAX, mn = FLT_MAX;
#pragma unroll
        for (int k = 0; k < KK; k++) {
            float uv = u[(size_t)sRow[bnl*KK + k]*CH2 + c];
            float val = w_part + uv;
            mx = fmaxf(mx, val); mn = fminf(mn, val);
            s += val; s2 += val*val;
        }
        xmax[(size_t)bn*CH2 + c] = mx;
        xmin[(size_t)bn*CH2 + c] = mn;
    }
    sS[tid] = s;
    __syncthreads();
    if (half == 0) atomicAdd(&slot[c], (double)(sS[c] + sS[c + 128]));
    __syncthreads();
    sS[tid] = s2;
    __syncthreads();
    if (half == 0) atomicAdd(&slot[CH2 + c], (double)(sS[c] + sS[c + 128]));
}

// ---------------- BN apply + rownorm + fp32 xn + bf16 hi/lo split ----------------
__global__ __launch_bounds__(256) void k_apply_norm(
    const float* __restrict__ pre, float* __restrict__ h,
    float* __restrict__ xn,
    __nv_bfloat16* __restrict__ xnh, __nv_bfloat16* __restrict__ xnl,
    float* __restrict__ sqv,
    const float* __restrict__ g, const float* __restrict__ bt,
    const double* __restrict__ slot)
{
    __shared__ float sSc[CCH], sSh[CCH];
    block_scale(slot, g, bt, CCH, M1, sSc, sSh);
    int wid = threadIdx.x >> 5, lane = threadIdx.x & 31;
    int r = blockIdx.x * 8 + wid;
    float2 v = ((const float2*)(pre + (size_t)r*CCH))[lane];
    float a  = v.x*sSc[lane*2]   + sSh[lane*2];
    float b2 = v.y*sSc[lane*2+1] + sSh[lane*2+1];
    ((float2*)(h + (size_t)r*CCH))[lane] = make_float2(a, b2);
    float ss = a*a + b2*b2;
#pragma unroll
    for (int o = 16; o > 0; o >>= 1) ss += __shfl_xor_sync(0xffffffff, ss, o);
    float inv = 1.0f / fmaxf(sqrtf(ss), 1e-12f);
    float x0v = a*inv, x1v = b2*inv;
    ((float2*)(xn + (size_t)r*CCH))[lane] = make_float2(x0v, x1v);
    __nv_bfloat16 h0 = __float2bfloat16(x0v);
    __nv_bfloat16 h1 = __float2bfloat16(x1v);
    __nv_bfloat16 l0 = __float2bfloat16(x0v - __bfloat162float(h0));
    __nv_bfloat16 l1 = __float2bfloat16(x1v - __bfloat162float(h1));
    __nv_bfloat162 ph; ph.x = h0; ph.y = h1;
    __nv_bfloat162 pl; pl.x = l0; pl.y = l1;
    ((__nv_bfloat162*)(xnh + (size_t)r*CCH))[lane] = ph;
    ((__nv_bfloat162*)(xnl + (size_t)r*CCH))[lane] = pl;
    if (lane == 0) sqv[r] = ss*inv*inv;
}

// ---------------- tensor-core KNN (approx filter) + exact fp32 refine ----------------
#define KROW 144
#define NCAND 16
#define KNNT_SMEM 55808
__global__ __launch_bounds__(256) void k_knn_tc(
    const float* __restrict__ xn,
    const __nv_bfloat16* __restrict__ xh, const __nv_bfloat16* __restrict__ xl,
    const float* __restrict__ sqv, int* __restrict__ idxout)
{
    extern __shared__ char sm[];
    uint32_t sb = smem_u32(sm);
    const uint32_t oAh = 0, oAl = 9216, oJh = 18432, oJl = 36864;
    float* sqj = (float*)(sm + 55296);

    int tid = threadIdx.x, lane = tid & 31, wid = tid >> 5;
    int qg = wid & 3, jhalf = wid >> 2;
    int b = blockIdx.x >> 6, qt = blockIdx.x & 63;
    int qbase = qt * 64;
    size_t boff = (size_t)b * NN;

    // stage A (64 query rows, hi+lo)
#pragma unroll
    for (int l = 0; l < 2; l++) {
        int e = tid + l*256;
        int row = e >> 3, seg = e & 7;
        uint32_t doff = (uint32_t)row*KROW + (uint32_t)seg*16;
        size_t gidx = (boff + qbase + row)*CCH + seg*8;
        *(uint4*)(sm + oAh + doff) = *(const uint4*)(xh + gidx);
        *(uint4*)(sm + oAl + doff) = *(const uint4*)(xl + gidx);
    }
    __syncthreads();

    uint32_t afh[4][4], afl[4][4];
    {
        uint32_t arow = (uint32_t)(qg*16 + (lane & 7) + ((lane >> 3) & 1)*8);
        uint32_t acol = (uint32_t)(((lane >> 4) & 1)*16);
#pragma unroll
        for (int ks = 0; ks < 4; ks++) {
            uint32_t ad = sb + arow*KROW + acol + (uint32_t)ks*32;
            ldsm_x4(afh[ks][0], afh[ks][1], afh[ks][2], afh[ks][3], ad + oAh);
            ldsm_x4(afl[ks][0], afl[ks][1], afl[ks][2], afl[ks][3], ad + oAl);
        }
    }

    int g = lane >> 2, tg = lane & 3;
    int q0 = qg*16 + g;
    float sqi0 = sqv[boff + qbase + q0];
    float sqi1 = sqv[boff + qbase + q0 + 8];

    float bd[2][9]; int bi[2][9];
#pragma unroll
    for (int hh = 0; hh < 2; hh++)
#pragma unroll
        for (int k = 0; k < 9; k++) { bd[hh][k] = FLT_MAX; bi[hh][k] = 0x7fffffff; }

    uint32_t brow_in = (uint32_t)(lane & 7);
    uint32_t bcol = (uint32_t)(((lane >> 3) & 1)*16);

    for (int jt = 0; jt < 32; jt++) {
        __syncthreads();
#pragma unroll
        for (int l = 0; l < 4; l++) {
            int e = tid + l*256;
            int row = e >> 3, seg = e & 7;
            uint32_t doff = (uint32_t)row*KROW + (uint32_t)seg*16;
            size_t gidx = (boff + (size_t)jt*128 + row)*CCH + seg*8;
            *(uint4*)(sm + oJh + doff) = *(const uint4*)(xh + gidx);
            *(uint4*)(sm + oJl + doff) = *(const uint4*)(xl + gidx);
        }
        if (tid < 128) sqj[tid] = sqv[boff + (size_t)jt*128 + tid];
        __syncthreads();

#pragma unroll
        for (int i = 0; i < 8; i++) {
            int nb = jhalf*8 + i;
            uint32_t badd = sb + ((uint32_t)(nb*8) + brow_in)*KROW + bcol;
            float d0 = 0.f, d1 = 0.f, d2 = 0.f, d3 = 0.f;
#pragma unroll
            for (int ks = 0; ks < 4; ks++) {
                uint32_t bh0, bh1, bl0, bl1;
                ldsm_x2(bh0, bh1, badd + oJh + (uint32_t)ks*32);
                ldsm_x2(bl0, bl1, badd + oJl + (uint32_t)ks*32);
                mma16816(d0, d1, d2, d3, afh[ks], bh0, bh1);
                mma16816(d0, d1, d2, d3, afl[ks], bh0, bh1);
                mma16816(d0, d1, d2, d3, afh[ks], bl0, bl1);
            }
            int jl = nb*8 + tg*2;
            int jg = jt*128 + jl;
            float sq0 = sqj[jl], sq1 = sqj[jl + 1];
#pragma unroll
            for (int e4 = 0; e4 < 4; e4++) {
                int hh = e4 >> 1;
                float dot = (e4 == 0) ? d0 : (e4 == 1) ? d1 : (e4 == 2) ? d2 : d3;
                float sqa = (hh == 0) ? sqi0 : sqi1;
                float sqb = (e4 & 1) ? sq1 : sq0;
                int jidx = jg + (e4 & 1);
                float dist = fmaf(-2.0f, dot, sqa + sqb);
                if (dist < bd[hh][8]) {
                    float dc = dist; int ic = jidx;
#pragma unroll
                    for (int k = 0; k < 9; k++) {
                        if (dc < bd[hh][k]) {
                            float td = bd[hh][k]; int ti = bi[hh][k];
                            bd[hh][k] = dc; bi[hh][k] = ic; dc = td; ic = ti;
                        }
                    }
                }
            }
        }
    }

    // merge 8 partitions -> top-NCAND approximate candidates, then exact refine
    __syncthreads();
    float* mD = (float*)sm;                    // [64][8][9]
    int*   mI = (int*)(sm + 18432);            // [64][8][9]
    int*   cI = (int*)(sm + 36864);            // [64][NCAND]
    float* cD = (float*)(sm + 36864 + 64*NCAND*4);  // [64][NCAND]
    int p = jhalf*4 + tg;
#pragma unroll
    for (int k = 0; k < 9; k++) {
        mD[(q0*8 + p)*9 + k]       = bd[0][k];
        mI[(q0*8 + p)*9 + k]       = bi[0][k];
        mD[((q0+8)*8 + p)*9 + k]   = bd[1][k];
        mI[((q0+8)*8 + p)*9 + k]   = bi[1][k];
    }
    __syncthreads();
    if (tid < 64) {
        int q = tid;
        int ptr[8];
#pragma unroll
        for (int pp = 0; pp < 8; pp++) ptr[pp] = 0;
        for (int k = 0; k < NCAND; k++) {
            float bestd = FLT_MAX; int besti = 0x7fffffff; int bp = 0;
#pragma unroll
            for (int pp = 0; pp < 8; pp++) {
                int hh = ptr[pp];
                if (hh < 9) {
                    float dc = mD[(q*8 + pp)*9 + hh];
                    int   ic = mI[(q*8 + pp)*9 + hh];
                    if (dc < bestd || (dc == bestd && ic < besti)) {
                        bestd = dc; besti = ic; bp = pp;
                    }
                }
            }
            cI[q*NCAND + k] = besti;
            ptr[bp]++;
        }
    }
    __syncthreads();
    // exact fp32 distances: 4 threads per query, 4 candidates each
    {
        int q = tid >> 2, sub = tid & 3;
        const float* xq = xn + (boff + qbase + q)*CCH;
        float sqq = sqv[boff + qbase + q];
#pragma unroll
        for (int cc = 0; cc < 4; cc++) {
            int slot = sub*4 + cc;
            int cand = cI[q*NCAND + slot];
            const float* xj = xn + (boff + cand)*CCH;
            float a0=0.f, a1=0.f, a2=0.f, a3=0.f;
#pragma unroll
            for (int c4 = 0; c4 < 16; c4++) {
                float4 qv = *(const float4*)(xq + c4*4);
                float4 jv = *(const float4*)(xj + c4*4);
                a0 += qv.x*jv.x; a1 += qv.y*jv.y; a2 += qv.z*jv.z; a3 += qv.w*jv.w;
            }
            float dot = (a0+a1) + (a2+a3);
            cD[q*NCAND + slot] = sqq - 2.0f*dot + sqv[boff + cand];
        }
    }
    __syncthreads();
    if (tid < 64) {
        int q = tid;
        float dl[NCAND]; int il[NCAND];
#pragma unroll
        for (int k = 0; k < NCAND; k++) { dl[k] = cD[q*NCAND + k]; il[k] = cI[q*NCAND + k]; }
#pragma unroll
        for (int k = 1; k < NCAND; k++) {
            float dk = dl[k]; int ik = il[k];
            int m = k;
#pragma unroll
            for (int jj = NCAND - 1; jj >= 1; jj--) {
                if (jj <= k) {
                    bool sm2 = (dk < dl[jj-1]) || (dk == dl[jj-1] && ik < il[jj-1]);
                    if (sm2) { dl[jj] = dl[jj-1]; il[jj] = il[jj-1]; m = jj - 1; }
                    else break;
                }
            }
            dl[m] = dk; il[m] = ik;
        }
        int* outI = idxout + (boff + qbase + q)*KK;
#pragma unroll
        for (int k = 0; k < KK; k++) outI[k] = il[k];
    }
}

// ---------------- final: BN(pref2)+res per branch, alpha mix, transpose ----------------
__global__ __launch_bounds__(256) void k_final(
    const float* __restrict__ alpha,
    const float* __restrict__ pref2, const float* __restrict__ res,
    const float* __restrict__ gf2, const float* __restrict__ btf2,
    const double* __restrict__ stats,
    float* __restrict__ out)
{
    __shared__ float sSc[2][CCH], sSh[2][CCH];
    __shared__ float t0[32][33], t1[32][33];
    int tx = threadIdx.x, ty = threadIdx.y;
    int tid = ty*32 + tx;
    for (int i = tid; i < 2*CCH; i += 256) {
        int t = i >> 6, c = i & 63;
        const double* slot = stats + (t*5 + 4)*512;
        double mean = slot[c] / (double)M1;
        double var  = slot[CCH + c] / (double)M1 - mean*mean;
        float sc = gf2[t*CCH + c] * rsqrtf((float)var + 1e-5f);
        sSc[t][c] = sc;
        sSh[t][c] = btf2[t*CCH + c] - (float)mean * sc;
    }
    __syncthreads();
    int b  = blockIdx.z;
    int n0 = blockIdx.x * 32, c0 = blockIdx.y * 32;
#pragma unroll
    for (int i = ty; i < 32; i += 8) {
        size_t e0 = ((size_t)b*NN + n0 + i)*CCH + c0 + tx;
        size_t e1 = (size_t)M1*CCH + e0;
        int c = c0 + tx;
        t0[i][tx] = pref2[e0]*sSc[0][c] + sSh[0][c] + res[e0];
        t1[i][tx] = pref2[e1]*sSc[1][c] + sSh[1][c] + res[e1];
    }
    __syncthreads();
    float a00 = alpha[0], a01 = alpha[1], a10 = alpha[2], a11 = alpha[3];
#pragma unroll
    for (int i = ty; i < 32; i += 8) {
        float f0 = t0[tx][i], f1 = t1[tx][i];
        out[(((size_t)0*BB + b)*CCH + c0 + i)*NN + n0 + tx] = a00*f0 + a01*f1;
        out[(((size_t)1*BB + b)*CCH + c0 + i)*NN + n0 + tx] = a10*f0 + a11*f1;
    }
}

// ---------------- host ----------------
struct BranchPtrs {
    float *hpre, *h, *xn, *sqv, *u, *v, *xmax, *xmin, *pre2, *res, *pref1, *pref2;
    __nv_bfloat16 *xnh, *xnl;
    int *idx;
};

extern "C" void kernel_launch(void* const* d_in, const int* in_sizes, int n_in,
                              void* d_out, int out_size) {
    (void)in_sizes; (void)n_in; (void)out_size;
    const float* x    = (const float*)d_in[0];
    const float* W1   = (const float*)d_in[1];
    const float* b1   = (const float*)d_in[2];
    const float* g1   = (const float*)d_in[3];
    const float* bt1  = (const float*)d_in[4];
    const float* Wg   = (const float*)d_in[5];
    const float* bg   = (const float*)d_in[6];
    const float* gg   = (const float*)d_in[7];
    const float* btg  = (const float*)d_in[8];
    const float* W2   = (const float*)d_in[9];
    const float* b2   = (const float*)d_in[10];
    const float* g2   = (const float*)d_in[11];
    const float* bt2  = (const float*)d_in[12];
    const float* Wf1  = (const float*)d_in[13];
    const float* bf1  = (const float*)d_in[14];
    const float* gf1  = (const float*)d_in[15];
    const float* btf1 = (const float*)d_in[16];
    const float* Wf2  = (const float*)d_in[17];
    const float* bf2  = (const float*)d_in[18];
    const float* gf2  = (const float*)d_in[19];
    const float* btf2 = (const float*)d_in[20];
    const float* alpha= (const float*)d_in[21];
    float* out = (float*)d_out;

    static cudaStream_t sB2[TT] = {nullptr, nullptr};
    static cudaEvent_t evF = nullptr, evJ[TT] = {nullptr, nullptr};
    static bool attrSet = false;
    if (!sB2[0]) {
        cudaStreamCreateWithFlags(&sB2[0], cudaStreamNonBlocking);
        cudaStreamCreateWithFlags(&sB2[1], cudaStreamNonBlocking);
        cudaEventCreateWithFlags(&evF, cudaEventDisableTiming);
        cudaEventCreateWithFlags(&evJ[0], cudaEventDisableTiming);
        cudaEventCreateWithFlags(&evJ[1], cudaEventDisableTiming);
    }
    if (!attrSet) {
        cudaFuncSetAttribute(k_knn_tc, cudaFuncAttributeMaxDynamicSharedMemorySize, KNNT_SMEM);
        attrSet = true;
    }

    float *p_x0;
    double* p_stats;
    cudaGetSymbolAddress((void**)&p_x0, d_x0);
    cudaGetSymbolAddress((void**)&p_stats, d_stats);

    BranchPtrs bp[TT];
    {
        float *base;
        cudaGetSymbolAddress((void**)&base, d_hpre);
        for (int t = 0; t < TT; t++) bp[t].hpre = base + (size_t)t*M1*CCH;
        cudaGetSymbolAddress((void**)&base, d_h);
        for (int t = 0; t < TT; t++) bp[t].h = base + (size_t)t*M1*CCH;
        cudaGetSymbolAddress((void**)&base, d_xn);
        for (int t = 0; t < TT; t++) bp[t].xn = base + (size_t)t*M1*CCH;
        cudaGetSymbolAddress((void**)&base, d_sqv);
        for (int t = 0; t < TT; t++) bp[t].sqv = base + (size_t)t*M1;
        cudaGetSymbolAddress((void**)&base, d_u);
        for (int t = 0; t < TT; t++) bp[t].u = base + (size_t)t*M1*CH2;
        cudaGetSymbolAddress((void**)&base, d_v);
        for (int t = 0; t < TT; t++) bp[t].v = base + (size_t)t*M1*CH2;
        cudaGetSymbolAddress((void**)&base, d_xmax);
        for (int t = 0; t < TT; t++) bp[t].xmax = base + (size_t)t*M1*CH2;
        cudaGetSymbolAddress((void**)&base, d_xmin);
        for (int t = 0; t < TT; t++) bp[t].xmin = base + (size_t)t*M1*CH2;
        cudaGetSymbolAddress((void**)&base, d_pre2);
        for (int t = 0; t < TT; t++) bp[t].pre2 = base + (size_t)t*M1*CCH;
        cudaGetSymbolAddress((void**)&base, d_res);
        for (int t = 0; t < TT; t++) bp[t].res = base + (size_t)t*M1*CCH;
        cudaGetSymbolAddress((void**)&base, d_pref1);
        for (int t = 0; t < TT; t++) bp[t].pref1 = base + (size_t)t*M1*CH4;
        cudaGetSymbolAddress((void**)&base, d_pref2);
        for (int t = 0; t < TT; t++) bp[t].pref2 = base + (size_t)t*M1*CCH;
        __nv_bfloat16* hb;
        cudaGetSymbolAddress((void**)&hb, d_xnh);
        for (int t = 0; t < TT; t++) bp[t].xnh = hb + (size_t)t*M1*CCH;
        cudaGetSymbolAddress((void**)&hb, d_xnl);
        for (int t = 0; t < TT; t++) bp[t].xnl = hb + (size_t)t*M1*CCH;
        int* ibase;
        cudaGetSymbolAddress((void**)&ibase, d_idx);
        for (int t = 0; t < TT; t++) bp[t].idx = ibase + (size_t)t*M1*KK;
    }

    k_zero_stats_all<<<1, 512>>>();
    k_transpose_in<<<dim3(NN/32, CCH/32, BB), dim3(32, 8)>>>(x, p_x0);

    cudaEventRecord(evF, 0);
    cudaStreamWaitEvent(sB2[0], evF, 0);
    cudaStreamWaitEvent(sB2[1], evF, 0);

    for (int t = 0; t < TT; t++) {
        cudaStream_t st = sB2[t];
        BranchPtrs& p = bp[t];
        double* s_bn1  = p_stats + (t*5 + 0)*512;
        double* s_bng  = p_stats + (t*5 + 1)*512;
        double* s_bn2  = p_stats + (t*5 + 2)*512;
        double* s_bnf1 = p_stats + (t*5 + 3)*512;
        double* s_bnf2 = p_stats + (t*5 + 4)*512;

        k_gemm<0><<<dim3(1, M1/64), 256, 0, st>>>(
            p_x0, nullptr, W1 + (size_t)t*CCH*CCH, b1 + t*CCH,
            p.hpre, s_bn1, CCH, CCH, nullptr, nullptr, nullptr, 1, nullptr);
        k_apply_norm<<<M1/8, 256, 0, st>>>(p.hpre, p.h, p.xn, p.xnh, p.xnl, p.sqv,
                                           g1 + t*CCH, bt1 + t*CCH, s_bn1);
        k_knn_tc<<<BB*(NN/64), 256, KNNT_SMEM, st>>>(p.xn, p.xnh, p.xnl, p.sqv, p.idx);
        k_uv<<<dim3(1, M1/128, 2), 256, 0, st>>>(p.h, Wg + (size_t)t*CH2*CH2, p.u, p.v);
        k_gather<<<M1/32, 256, 0, st>>>(p.u, p.v, p.idx, bg + t*CH2,
                                        p.xmax, p.xmin, s_bng);
        k_gemm<1><<<dim3(1, M1/64), 256, 0, st>>>(
            p.xmax, p.xmin, W2 + (size_t)t*CH2*CCH, b2 + t*CCH,
            p.pre2, s_bn2, CH2, CCH, s_bng, gg + t*CH2, btg + t*CH2, MG, nullptr);
        k_gemm<3><<<dim3(CH4/64, M1/64), 256, 0, st>>>(
            p.pre2, p_x0, Wf1 + (size_t)t*CCH*CH4, bf1 + t*CH4,
            p.pref1, s_bnf1, CCH, CH4, s_bn2, g2 + t*CCH, bt2 + t*CCH, M1, p.res);
        k_gemm<2><<<dim3(1, M1/64), 256, 0, st>>>(
            p.pref1, nullptr, Wf2 + (size_t)t*CH4*CCH, bf2 + t*CCH,
            p.pref2, s_bnf2, CH4, CCH, s_bnf1, gf1 + t*CH4, btf1 + t*CH4, M1, nullptr);
        cudaEventRecord(evJ[t], st);
    }

    cudaStreamWaitEvent(0, evJ[0], 0);
    cudaStreamWaitEvent(0, evJ[1], 0);

    k_final<<<dim3(NN/32, CCH/32, BB), dim3(32, 8)>>>(alpha, bp[0].pref2, bp[0].res,
                                                      gf2, btf2, p_stats, out);
}

// round 17
// speedup vs baseline: 1.5379x; 1.0007x over previous
#include <cuda_runtime.h>
#include <cuda_bf16.h>
#include <stdint.h>
#include <math.h>
#include <float.h>

#define BB  2
#define CCH 64
#define NN  4096
#define KK  9
#define TT  2
#define CH2 128
#define CH4 256
#define M1  (BB*NN)          // 8192
#define MG  (BB*NN*KK)       // 73728

typedef unsigned long long ull;

// ---------------- scratch (per-branch double buffered) ----------------
__device__ float  d_x0[M1*CCH];
__device__ float  d_hpre[TT][M1*CCH];
__device__ float  d_h[TT][M1*CCH];
__device__ float  d_xn[TT][M1*CCH];
__device__ __nv_bfloat16 d_xnh[TT][M1*CCH];
__device__ __nv_bfloat16 d_xnl[TT][M1*CCH];
__device__ float  d_sqv[TT][M1];
__device__ int    d_idx[TT][M1*KK];
__device__ float  d_u[TT][M1*CH2];
__device__ float  d_v[TT][M1*CH2];
__device__ float  d_xmax[TT][M1*CH2];
__device__ float  d_xmin[TT][M1*CH2];
__device__ float  d_pre2[TT][M1*CCH];
__device__ float  d_res[TT][M1*CCH];
__device__ float  d_pref1[TT][(size_t)M1*CH4];
__device__ float  d_pref2[TT][M1*CCH];
__device__ double d_stats[10*512];

// ---------------- packed f32x2 helpers ----------------
__device__ __forceinline__ void ffma2(ull& d, ull a, ull b) {
    asm("fma.rn.f32x2 %0, %1, %2, %0;" : "+l"(d) : "l"(a), "l"(b));
}
__device__ __forceinline__ ull dup_f32(float x) {
    ull r; asm("mov.b64 %0, {%1, %1};" : "=l"(r) : "f"(x)); return r;
}
__device__ __forceinline__ float2 unpack2(ull v) {
    float2 r; asm("mov.b64 {%0, %1}, %2;" : "=f"(r.x), "=f"(r.y) : "l"(v)); return r;
}

__device__ __forceinline__ float gelu_exact(float x) {
    return 0.5f * x * (1.0f + erff(x * 0.70710678118654752f));
}

__device__ __forceinline__ void block_scale(const double* __restrict__ slot,
                                            const float* __restrict__ g,
                                            const float* __restrict__ bt,
                                            int Cc, int M,
                                            float* sSc, float* sSh)
{
    for (int c = threadIdx.x; c < Cc; c += blockDim.x) {
        double mean = slot[c] / (double)M;
        double var  = slot[Cc + c] / (double)M - mean*mean;
        float sc = g[c] * rsqrtf((float)var + 1e-5f);
        sSc[c] = sc;
        sSh[c] = bt[c] - (float)mean * sc;
    }
    __syncthreads();
}

__global__ void k_zero_stats_all() {
    for (int i = threadIdx.x; i < 10*512; i += blockDim.x) d_stats[i] = 0.0;
}

// ---------------- warp mma helpers ----------------
__device__ __forceinline__ uint32_t smem_u32(const void* p) {
    uint32_t a;
    asm("{ .reg .u64 t; cvta.to.shared.u64 t, %1; cvt.u32.u64 %0, t; }" : "=r"(a) : "l"(p));
    return a;
}
__device__ __forceinline__ void ldsm_x4(uint32_t& r0, uint32_t& r1, uint32_t& r2, uint32_t& r3,
                                        uint32_t addr) {
    asm volatile("ldmatrix.sync.aligned.m8n8.x4.shared.b16 {%0,%1,%2,%3}, [%4];"
                 : "=r"(r0), "=r"(r1), "=r"(r2), "=r"(r3) : "r"(addr));
}
__device__ __forceinline__ void mma16816(float& d0, float& d1, float& d2, float& d3,
                                         const uint32_t* a, uint32_t b0, uint32_t b1) {
    asm volatile(
        "mma.sync.aligned.m16n8k16.row.col.f32.bf16.bf16.f32 "
        "{%0,%1,%2,%3}, {%4,%5,%6,%7}, {%8,%9}, {%0,%1,%2,%3};"
        : "+f"(d0), "+f"(d1), "+f"(d2), "+f"(d3)
        : "r"(a[0]), "r"(a[1]), "r"(a[2]), "r"(a[3]), "r"(b0), "r"(b1));
}

// ---------------- tiled transpose x (B,C,N) -> x0 (B,N,C) ----------------
__global__ __launch_bounds__(256) void k_transpose_in(const float* __restrict__ x,
                                                      float* __restrict__ x0) {
    __shared__ float tile[32][33];
    int b  = blockIdx.z;
    int n0 = blockIdx.x * 32, c0 = blockIdx.y * 32;
    int tx = threadIdx.x, ty = threadIdx.y;
#pragma unroll
    for (int i = ty; i < 32; i += 8)
        tile[i][tx] = x[((size_t)b*CCH + c0 + i)*NN + n0 + tx];
    __syncthreads();
#pragma unroll
    for (int i = ty; i < 32; i += 8)
        x0[((size_t)b*NN + n0 + i)*CCH + c0 + tx] = tile[tx][i];
}

// ---------------- GEMM BM=64 BN=64 BK=16, fused input/epilogue ----------------
template<int MODE>
__global__ __launch_bounds__(256) void k_gemm(
    const float* __restrict__ A, const float* __restrict__ aux,
    const float* __restrict__ W, const float* __restrict__ bias,
    float* __restrict__ C, double* __restrict__ slotOut,
    int Kd, int Nd,
    const double* __restrict__ slotIn, const float* __restrict__ gIn,
    const float* __restrict__ btIn, int Min, float* __restrict__ resOut)
{
    __shared__ __align__(16) float sA[16][68];
    __shared__ __align__(16) float sB[16][68];
    __shared__ float sScIn[256], sShIn[256];
    int tid = threadIdx.x;
    int tx = tid & 15, ty = tid >> 4;
    int row0 = blockIdx.y * 64;
    int col0 = blockIdx.x * 64;

    if (MODE != 0) {
        for (int c = tid; c < Kd; c += 256) {
            double mean = slotIn[c] / (double)Min;
            double var  = slotIn[Kd + c] / (double)Min - mean*mean;
            float sc = gIn[c] * rsqrtf((float)var + 1e-5f);
            sScIn[c] = sc;
            sShIn[c] = btIn[c] - (float)mean * sc;
        }
        __syncthreads();
    }

    ull accp[2][4];
#pragma unroll
    for (int i = 0; i < 2; i++)
#pragma unroll
        for (int j = 0; j < 4; j++) accp[i][j] = 0ULL;

    for (int k0 = 0; k0 < Kd; k0 += 16) {
        {
            int r  = tid >> 2;
            int kk = (tid & 3) * 4;
            size_t base = (size_t)(row0 + r)*Kd + k0 + kk;
            float vv[4];
            if (MODE == 0) {
                float4 v = *(const float4*)(A + base);
                vv[0]=v.x; vv[1]=v.y; vv[2]=v.z; vv[3]=v.w;
            } else if (MODE == 1) {
                float4 vx = *(const float4*)(A + base);
                float4 vn = *(const float4*)(aux + base);
                float ax[4] = {vx.x, vx.y, vx.z, vx.w};
                float an[4] = {vn.x, vn.y, vn.z, vn.w};
#pragma unroll
                for (int i = 0; i < 4; i++) {
                    float sc = sScIn[k0+kk+i], sh = sShIn[k0+kk+i];
                    vv[i] = fmaxf(gelu_exact(ax[i]*sc + sh), gelu_exact(an[i]*sc + sh));
                }
            } else if (MODE == 2) {
                float4 vp = *(const float4*)(A + base);
                float ap[4] = {vp.x, vp.y, vp.z, vp.w};
#pragma unroll
                for (int i = 0; i < 4; i++)
                    vv[i] = gelu_exact(ap[i]*sScIn[k0+kk+i] + sShIn[k0+kk+i]);
            } else {
                float4 vp = *(const float4*)(A + base);
                float4 vr = *(const float4*)(aux + base);
                float ap[4] = {vp.x, vp.y, vp.z, vp.w};
                float ar[4] = {vr.x, vr.y, vr.z, vr.w};
#pragma unroll
                for (int i = 0; i < 4; i++)
                    vv[i] = ap[i]*sScIn[k0+kk+i] + sShIn[k0+kk+i] + ar[i];
                if (blockIdx.x == 0)
                    *(float4*)(resOut + base) = make_float4(vv[0], vv[1], vv[2], vv[3]);
            }
#pragma unroll
            for (int i = 0; i < 4; i++) sA[kk+i][r] = vv[i];
        }
        {
            int r  = tid >> 4;
            int nn = (tid & 15) * 4;
            float4 v = *(const float4*)(W + (size_t)(k0 + r)*Nd + col0 + nn);
            sB[r][nn+0] = v.x; sB[r][nn+1] = v.y; sB[r][nn+2] = v.z; sB[r][nn+3] = v.w;
        }
        __syncthreads();
#pragma unroll
        for (int k = 0; k < 16; k++) {
            ulonglong2 ra = *(const ulonglong2*)&sA[k][ty*4];
            float4 rbf = *(const float4*)&sB[k][tx*4];
            ull rb0 = dup_f32(rbf.x), rb1 = dup_f32(rbf.y);
            ull rb2 = dup_f32(rbf.z), rb3 = dup_f32(rbf.w);
            ffma2(accp[0][0], ra.x, rb0); ffma2(accp[0][1], ra.x, rb1);
            ffma2(accp[0][2], ra.x, rb2); ffma2(accp[0][3], ra.x, rb3);
            ffma2(accp[1][0], ra.y, rb0); ffma2(accp[1][1], ra.y, rb1);
            ffma2(accp[1][2], ra.y, rb2); ffma2(accp[1][3], ra.y, rb3);
        }
        __syncthreads();
    }
    float acc[4][4];
#pragma unroll
    for (int ip = 0; ip < 2; ip++)
#pragma unroll
        for (int j = 0; j < 4; j++) {
            float2 u = unpack2(accp[ip][j]);
            acc[2*ip][j] = u.x; acc[2*ip+1][j] = u.y;
        }
    float bb[4];
#pragma unroll
    for (int j = 0; j < 4; j++) bb[j] = bias[col0 + tx*4 + j];
#pragma unroll
    for (int i = 0; i < 4; i++) {
#pragma unroll
        for (int j = 0; j < 4; j++) acc[i][j] += bb[j];
        *(float4*)(C + (size_t)(row0 + ty*4 + i)*Nd + col0 + tx*4) =
            make_float4(acc[i][0], acc[i][1], acc[i][2], acc[i][3]);
    }
    float s[4], s2[4];
#pragma unroll
    for (int j = 0; j < 4; j++) {
        s[j] = 0.f; s2[j] = 0.f;
#pragma unroll
        for (int i = 0; i < 4; i++) { float v = acc[i][j]; s[j] += v; s2[j] += v*v; }
    }
    float* sRed = &sA[0][0];
    __syncthreads();
#pragma unroll
    for (int j = 0; j < 4; j++) sRed[ty*64 + tx*4 + j] = s[j];
    __syncthreads();
    if (tid < 64) {
        float tot = 0.f;
#pragma unroll
        for (int yy = 0; yy < 16; yy++) tot += sRed[yy*64 + tid];
        atomicAdd(&slotOut[col0 + tid], (double)tot);
    }
    __syncthreads();
#pragma unroll
    for (int j = 0; j < 4; j++) sRed[ty*64 + tx*4 + j] = s2[j];
    __syncthreads();
    if (tid < 64) {
        float tot = 0.f;
#pragma unroll
        for (int yy = 0; yy < 16; yy++) tot += sRed[yy*64 + tid];
        atomicAdd(&slotOut[Nd + col0 + tid], (double)tot);
    }
}

// ---------------- u/v GEMM ----------------
__global__ __launch_bounds__(256) void k_uv(
    const float* __restrict__ h, const float* __restrict__ Wg,
    float* __restrict__ u, float* __restrict__ v)
{
    __shared__ __align__(16) float sA[16][132];
    __shared__ __align__(16) float sB[16][132];
    int zs = blockIdx.z;
    const float* W = Wg + (zs == 0 ? (size_t)CCH*CH2 : 0);
    float* C = (zs == 0) ? u : v;
    int tid = threadIdx.x;
    int tx = tid & 15, ty = tid >> 4;
    int r0 = blockIdx.y * 128;
    ull accp[4][8];
#pragma unroll
    for (int i = 0; i < 4; i++)
#pragma unroll
        for (int j = 0; j < 8; j++) accp[i][j] = 0ULL;

    for (int k0 = 0; k0 < CCH; k0 += 16) {
#pragma unroll
        for (int l = 0; l < 2; l++) {
            int e = tid + l*256;
            int rr = e >> 2;
            int kk = (e & 3) * 4;
            float4 vv = *(const float4*)(h + (size_t)(r0 + rr)*CCH + k0 + kk);
            sA[kk+0][rr] = vv.x; sA[kk+1][rr] = vv.y; sA[kk+2][rr] = vv.z; sA[kk+3][rr] = vv.w;
        }
#pragma unroll
        for (int l = 0; l < 2; l++) {
            int e = tid + l*256;
            int rr = e >> 5;
            int nn = (e & 31) * 4;
            float4 vv = *(const float4*)(W + (size_t)(k0 + rr)*CH2 + nn);
            sB[rr][nn+0] = vv.x; sB[rr][nn+1] = vv.y; sB[rr][nn+2] = vv.z; sB[rr][nn+3] = vv.w;
        }
        __syncthreads();
#pragma unroll
        for (int k = 0; k < 16; k++) {
            ulonglong2 ra01 = *(const ulonglong2*)&sA[k][ty*8];
            ulonglong2 ra23 = *(const ulonglong2*)&sA[k][ty*8 + 4];
            float rbf[8];
            *(float4*)&rbf[0] = *(const float4*)&sB[k][tx*8];
            *(float4*)&rbf[4] = *(const float4*)&sB[k][tx*8 + 4];
            ull rap[4] = {ra01.x, ra01.y, ra23.x, ra23.y};
            ull rb[8];
#pragma unroll
            for (int j = 0; j < 8; j++) rb[j] = dup_f32(rbf[j]);
#pragma unroll
            for (int ip = 0; ip < 4; ip++)
#pragma unroll
                for (int j = 0; j < 8; j++) ffma2(accp[ip][j], rap[ip], rb[j]);
        }
        __syncthreads();
    }
#pragma unroll
    for (int ip = 0; ip < 4; ip++) {
        float acc0[8], acc1[8];
#pragma unroll
        for (int j = 0; j < 8; j++) {
            float2 uu = unpack2(accp[ip][j]);
            acc0[j] = uu.x; acc1[j] = uu.y;
        }
        float* cp0 = C + (size_t)(r0 + ty*8 + 2*ip)*CH2 + tx*8;
        float* cp1 = C + (size_t)(r0 + ty*8 + 2*ip + 1)*CH2 + tx*8;
        *(float4*)cp0       = make_float4(acc0[0], acc0[1], acc0[2], acc0[3]);
        *(float4*)(cp0 + 4) = make_float4(acc0[4], acc0[5], acc0[6], acc0[7]);
        *(float4*)cp1       = make_float4(acc1[0], acc1[1], acc1[2], acc1[3]);
        *(float4*)(cp1 + 4) = make_float4(acc1[4], acc1[5], acc1[6], acc1[7]);
    }
}

// ---------------- gather ----------------
__global__ __launch_bounds__(256) void k_gather(
    const float* __restrict__ u, const float* __restrict__ v,
    const int* __restrict__ idx, const float* __restrict__ bias,
    float* __restrict__ xmax, float* __restrict__ xmin,
    double* __restrict__ slot)
{
    __shared__ int sRow[32*KK];
    __shared__ float sS[256];
    int tid = threadIdx.x;
    int c = tid & 127, half = tid >> 7;
    int bn0 = blockIdx.x * 32;
    for (int i = tid; i < 32*KK; i += 256) {
        int bn = bn0 + i/KK;
        int j = idx[(size_t)bn0*KK + i];
        sRow[i] = (bn & 4096) + j;
    }
    __syncthreads();
    float bias_c = bias[c];
    float s = 0.f, s2 = 0.f;
#pragma unroll 2
    for (int pass = 0; pass < 16; pass++) {
        int bnl = pass*2 + half;
        int bn = bn0 + bnl;
        float w_part = v[(size_t)bn*CH2 + c] - u[(size_t)bn*CH2 + c] + bias_c;
        float mx = -FLT_MAX, mn = FLT_MAX;
#pragma unroll
        for (int k = 0; k < KK; k++) {
            float uv = u[(size_t)sRow[bnl*KK + k]*CH2 + c];
            float val = w_part + uv;
            mx = fmaxf(mx, val); mn = fminf(mn, val);
            s += val; s2 += val*val;
        }
        xmax[(size_t)bn*CH2 + c] = mx;
        xmin[(size_t)bn*CH2 + c] = mn;
    }
    sS[tid] = s;
    __syncthreads();
    if (half == 0) atomicAdd(&slot[c], (double)(sS[c] + sS[c + 128]));
    __syncthreads();
    sS[tid] = s2;
    __syncthreads();
    if (half == 0) atomicAdd(&slot[CH2 + c], (double)(sS[c] + sS[c + 128]));
}

// ---------------- BN apply + rownorm + fp32 xn + bf16 hi/lo split ----------------
__global__ __launch_bounds__(256) void k_apply_norm(
    const float* __restrict__ pre, float* __restrict__ h,
    float* __restrict__ xn,
    __nv_bfloat16* __restrict__ xnh, __nv_bfloat16* __restrict__ xnl,
    float* __restrict__ sqv,
    const float* __restrict__ g, const float* __restrict__ bt,
    const double* __restrict__ slot)
{
    __shared__ float sSc[CCH], sSh[CCH];
    block_scale(slot, g, bt, CCH, M1, sSc, sSh);
    int wid = threadIdx.x >> 5, lane = threadIdx.x & 31;
    int r = blockIdx.x * 8 + wid;
    float2 v = ((const float2*)(pre + (size_t)r*CCH))[lane];
    float a  = v.x*sSc[lane*2]   + sSh[lane*2];
    float b2 = v.y*sSc[lane*2+1] + sSh[lane*2+1];
    ((float2*)(h + (size_t)r*CCH))[lane] = make_float2(a, b2);
    float ss = a*a + b2*b2;
#pragma unroll
    for (int o = 16; o > 0; o >>= 1) ss += __shfl_xor_sync(0xffffffff, ss, o);
    float inv = 1.0f / fmaxf(sqrtf(ss), 1e-12f);
    float x0v = a*inv, x1v = b2*inv;
    ((float2*)(xn + (size_t)r*CCH))[lane] = make_float2(x0v, x1v);
    __nv_bfloat16 h0 = __float2bfloat16(x0v);
    __nv_bfloat16 h1 = __float2bfloat16(x1v);
    __nv_bfloat16 l0 = __float2bfloat16(x0v - __bfloat162float(h0));
    __nv_bfloat16 l1 = __float2bfloat16(x1v - __bfloat162float(h1));
    __nv_bfloat162 ph; ph.x = h0; ph.y = h1;
    __nv_bfloat162 pl; pl.x = l0; pl.y = l1;
    ((__nv_bfloat162*)(xnh + (size_t)r*CCH))[lane] = ph;
    ((__nv_bfloat162*)(xnl + (size_t)r*CCH))[lane] = pl;
    if (lane == 0) sqv[r] = ss*inv*inv;
}

// ---------------- tensor-core KNN (approx filter) + exact fp32 refine ----------------
#define KROW 144
#define NCAND 16
#define KNNT_SMEM 55808
__global__ __launch_bounds__(256) void k_knn_tc(
    const float* __restrict__ xn,
    const __nv_bfloat16* __restrict__ xh, const __nv_bfloat16* __restrict__ xl,
    const float* __restrict__ sqv, int* __restrict__ idxout)
{
    extern __shared__ char sm[];
    uint32_t sb = smem_u32(sm);
    const uint32_t oAh = 0, oAl = 9216, oJh = 18432, oJl = 36864;
    float* sqj = (float*)(sm + 55296);

    int tid = threadIdx.x, lane = tid & 31, wid = tid >> 5;
    int qg = wid & 3, jhalf = wid >> 2;
    int b = blockIdx.x >> 6, qt = blockIdx.x & 63;
    int qbase = qt * 64;
    size_t boff = (size_t)b * NN;

    // stage A (64 query rows, hi+lo)
#pragma unroll
    for (int l = 0; l < 2; l++) {
        int e = tid + l*256;
        int row = e >> 3, seg = e & 7;
        uint32_t doff = (uint32_t)row*KROW + (uint32_t)seg*16;
        size_t gidx = (boff + qbase + row)*CCH + seg*8;
        *(uint4*)(sm + oAh + doff) = *(const uint4*)(xh + gidx);
        *(uint4*)(sm + oAl + doff) = *(const uint4*)(xl + gidx);
    }
    __syncthreads();

    uint32_t afh[4][4], afl[4][4];
    {
        uint32_t arow = (uint32_t)(qg*16 + (lane & 7) + ((lane >> 3) & 1)*8);
        uint32_t acol = (uint32_t)(((lane >> 4) & 1)*16);
#pragma unroll
        for (int ks = 0; ks < 4; ks++) {
            uint32_t ad = sb + arow*KROW + acol + (uint32_t)ks*32;
            ldsm_x4(afh[ks][0], afh[ks][1], afh[ks][2], afh[ks][3], ad + oAh);
            ldsm_x4(afl[ks][0], afl[ks][1], afl[ks][2], afl[ks][3], ad + oAl);
        }
    }

    int g = lane >> 2, tg = lane & 3;
    int q0 = qg*16 + g;
    float sqi0 = sqv[boff + qbase + q0];
    float sqi1 = sqv[boff + qbase + q0 + 8];

    float bd[2][9]; int bi[2][9];
#pragma unroll
    for (int hh = 0; hh < 2; hh++)
#pragma unroll
        for (int k = 0; k < 9; k++) { bd[hh][k] = FLT_MAX; bi[hh][k] = 0x7fffffff; }

    // x4 B-operand addressing: matrix m = lane>>3 -> (ks_in = m>>1, col = (m&1)*16)
    uint32_t brow_in = (uint32_t)(lane & 7);
    uint32_t bcol4 = (uint32_t)(((lane >> 3) & 1)*16) + (uint32_t)(((lane >> 4) & 1)*32);

    for (int jt = 0; jt < 32; jt++) {
        __syncthreads();
#pragma unroll
        for (int l = 0; l < 4; l++) {
            int e = tid + l*256;
            int row = e >> 3, seg = e & 7;
            uint32_t doff = (uint32_t)row*KROW + (uint32_t)seg*16;
            size_t gidx = (boff + (size_t)jt*128 + row)*CCH + seg*8;
            *(uint4*)(sm + oJh + doff) = *(const uint4*)(xh + gidx);
            *(uint4*)(sm + oJl + doff) = *(const uint4*)(xl + gidx);
        }
        if (tid < 128) sqj[tid] = sqv[boff + (size_t)jt*128 + tid];
        __syncthreads();

#pragma unroll
        for (int i = 0; i < 8; i++) {
            int nb = jhalf*8 + i;
            uint32_t badd = sb + ((uint32_t)(nb*8) + brow_in)*KROW + bcol4;
            float d0 = 0.f, d1 = 0.f, d2 = 0.f, d3 = 0.f;
#pragma unroll
            for (int ksp = 0; ksp < 2; ksp++) {
                uint32_t bh[4], bl[4];
                ldsm_x4(bh[0], bh[1], bh[2], bh[3], badd + oJh + (uint32_t)ksp*64);
                ldsm_x4(bl[0], bl[1], bl[2], bl[3], badd + oJl + (uint32_t)ksp*64);
                int ks0 = 2*ksp;
                mma16816(d0, d1, d2, d3, afh[ks0],   bh[0], bh[1]);
                mma16816(d0, d1, d2, d3, afl[ks0],   bh[0], bh[1]);
                mma16816(d0, d1, d2, d3, afh[ks0],   bl[0], bl[1]);
                mma16816(d0, d1, d2, d3, afh[ks0+1], bh[2], bh[3]);
                mma16816(d0, d1, d2, d3, afl[ks0+1], bh[2], bh[3]);
                mma16816(d0, d1, d2, d3, afh[ks0+1], bl[2], bl[3]);
            }
            int jl = nb*8 + tg*2;
            int jg = jt*128 + jl;
            float sq0 = sqj[jl], sq1 = sqj[jl + 1];
#pragma unroll
            for (int e4 = 0; e4 < 4; e4++) {
                int hh = e4 >> 1;
                float dot = (e4 == 0) ? d0 : (e4 == 1) ? d1 : (e4 == 2) ? d2 : d3;
                float sqa = (hh == 0) ? sqi0 : sqi1;
                float sqb = (e4 & 1) ? sq1 : sq0;
                int jidx = jg + (e4 & 1);
                float dist = fmaf(-2.0f, dot, sqa + sqb);
                if (dist < bd[hh][8]) {
                    float dc = dist; int ic = jidx;
#pragma unroll
                    for (int k = 0; k < 9; k++) {
                        if (dc < bd[hh][k]) {
                            float td = bd[hh][k]; int ti = bi[hh][k];
                            bd[hh][k] = dc; bi[hh][k] = ic; dc = td; ic = ti;
                        }
                    }
                }
            }
        }
    }

    // merge 8 partitions -> top-NCAND approximate candidates, then exact refine
    __syncthreads();
    float* mD = (float*)sm;                    // [64][8][9]
    int*   mI = (int*)(sm + 18432);            // [64][8][9]
    int*   cI = (int*)(sm + 36864);            // [64][NCAND]
    float* cD = (float*)(sm + 36864 + 64*NCAND*4);  // [64][NCAND]
    int p = jhalf*4 + tg;
#pragma unroll
    for (int k = 0; k < 9; k++) {
        mD[(q0*8 + p)*9 + k]       = bd[0][k];
        mI[(q0*8 + p)*9 + k]       = bi[0][k];
        mD[((q0+8)*8 + p)*9 + k]   = bd[1][k];
        mI[((q0+8)*8 + p)*9 + k]   = bi[1][k];
    }
    __syncthreads();
    if (tid < 64) {
        int q = tid;
        int ptr[8];
#pragma unroll
        for (int pp = 0; pp < 8; pp++) ptr[pp] = 0;
        for (int k = 0; k < NCAND; k++) {
            float bestd = FLT_MAX; int besti = 0x7fffffff; int bp = 0;
#pragma unroll
            for (int pp = 0; pp < 8; pp++) {
                int hh = ptr[pp];
                if (hh < 9) {
                    float dc = mD[(q*8 + pp)*9 + hh];
                    int   ic = mI[(q*8 + pp)*9 + hh];
                    if (dc < bestd || (dc == bestd && ic < besti)) {
                        bestd = dc; besti = ic; bp = pp;
                    }
                }
            }
            cI[q*NCAND + k] = besti;
            ptr[bp]++;
        }
    }
    __syncthreads();
    // exact fp32 distances: 4 threads per query, 4 candidates each
    {
        int q = tid >> 2, sub = tid & 3;
        const float* xq = xn + (boff + qbase + q)*CCH;
        float sqq = sqv[boff + qbase + q];
#pragma unroll
        for (int cc = 0; cc < 4; cc++) {
            int slot = sub*4 + cc;
            int cand = cI[q*NCAND + slot];
            const float* xj = xn + (boff + cand)*CCH;
            float a0=0.f, a1=0.f, a2=0.f, a3=0.f;
#pragma unroll
            for (int c4 = 0; c4 < 16; c4++) {
                float4 qv = *(const float4*)(xq + c4*4);
                float4 jv = *(const float4*)(xj + c4*4);
                a0 += qv.x*jv.x; a1 += qv.y*jv.y; a2 += qv.z*jv.z; a3 += qv.w*jv.w;
            }
            float dot = (a0+a1) + (a2+a3);
            cD[q*NCAND + slot] = sqq - 2.0f*dot + sqv[boff + cand];
        }
    }
    __syncthreads();
    if (tid < 64) {
        int q = tid;
        float dl[NCAND]; int il[NCAND];
#pragma unroll
        for (int k = 0; k < NCAND; k++) { dl[k] = cD[q*NCAND + k]; il[k] = cI[q*NCAND + k]; }
#pragma unroll
        for (int k = 1; k < NCAND; k++) {
            float dk = dl[k]; int ik = il[k];
            int m = k;
#pragma unroll
            for (int jj = NCAND - 1; jj >= 1; jj--) {
                if (jj <= k) {
                    bool sm2 = (dk < dl[jj-1]) || (dk == dl[jj-1] && ik < il[jj-1]);
                    if (sm2) { dl[jj] = dl[jj-1]; il[jj] = il[jj-1]; m = jj - 1; }
                    else break;
                }
            }
            dl[m] = dk; il[m] = ik;
        }
        int* outI = idxout + (boff + qbase + q)*KK;
#pragma unroll
        for (int k = 0; k < KK; k++) outI[k] = il[k];
    }
}

// ---------------- final: BN(pref2)+res per branch, alpha mix, transpose ----------------
__global__ __launch_bounds__(256) void k_final(
    const float* __restrict__ alpha,
    const float* __restrict__ pref2, const float* __restrict__ res,
    const float* __restrict__ gf2, const float* __restrict__ btf2,
    const double* __restrict__ stats,
    float* __restrict__ out)
{
    __shared__ float sSc[2][CCH], sSh[2][CCH];
    __shared__ float t0[32][33], t1[32][33];
    int tx = threadIdx.x, ty = threadIdx.y;
    int tid = ty*32 + tx;
    for (int i = tid; i < 2*CCH; i += 256) {
        int t = i >> 6, c = i & 63;
        const double* slot = stats + (t*5 + 4)*512;
        double mean = slot[c] / (double)M1;
        double var  = slot[CCH + c] / (double)M1 - mean*mean;
        float sc = gf2[t*CCH + c] * rsqrtf((float)var + 1e-5f);
        sSc[t][c] = sc;
        sSh[t][c] = btf2[t*CCH + c] - (float)mean * sc;
    }
    __syncthreads();
    int b  = blockIdx.z;
    int n0 = blockIdx.x * 32, c0 = blockIdx.y * 32;
#pragma unroll
    for (int i = ty; i < 32; i += 8) {
        size_t e0 = ((size_t)b*NN + n0 + i)*CCH + c0 + tx;
        size_t e1 = (size_t)M1*CCH + e0;
        int c = c0 + tx;
        t0[i][tx] = pref2[e0]*sSc[0][c] + sSh[0][c] + res[e0];
        t1[i][tx] = pref2[e1]*sSc[1][c] + sSh[1][c] + res[e1];
    }
    __syncthreads();
    float a00 = alpha[0], a01 = alpha[1], a10 = alpha[2], a11 = alpha[3];
#pragma unroll
    for (int i = ty; i < 32; i += 8) {
        float f0 = t0[tx][i], f1 = t1[tx][i];
        out[(((size_t)0*BB + b)*CCH + c0 + i)*NN + n0 + tx] = a00*f0 + a01*f1;
        out[(((size_t)1*BB + b)*CCH + c0 + i)*NN + n0 + tx] = a10*f0 + a11*f1;
    }
}

// ---------------- host ----------------
struct BranchPtrs {
    float *hpre, *h, *xn, *sqv, *u, *v, *xmax, *xmin, *pre2, *res, *pref1, *pref2;
    __nv_bfloat16 *xnh, *xnl;
    int *idx;
};

extern "C" void kernel_launch(void* const* d_in, const int* in_sizes, int n_in,
                              void* d_out, int out_size) {
    (void)in_sizes; (void)n_in; (void)out_size;
    const float* x    = (const float*)d_in[0];
    const float* W1   = (const float*)d_in[1];
    const float* b1   = (const float*)d_in[2];
    const float* g1   = (const float*)d_in[3];
    const float* bt1  = (const float*)d_in[4];
    const float* Wg   = (const float*)d_in[5];
    const float* bg   = (const float*)d_in[6];
    const float* gg   = (const float*)d_in[7];
    const float* btg  = (const float*)d_in[8];
    const float* W2   = (const float*)d_in[9];
    const float* b2   = (const float*)d_in[10];
    const float* g2   = (const float*)d_in[11];
    const float* bt2  = (const float*)d_in[12];
    const float* Wf1  = (const float*)d_in[13];
    const float* bf1  = (const float*)d_in[14];
    const float* gf1  = (const float*)d_in[15];
    const float* btf1 = (const float*)d_in[16];
    const float* Wf2  = (const float*)d_in[17];
    const float* bf2  = (const float*)d_in[18];
    const float* gf2  = (const float*)d_in[19];
    const float* btf2 = (const float*)d_in[20];
    const float* alpha= (const float*)d_in[21];
    float* out = (float*)d_out;

    static cudaStream_t sB2[TT] = {nullptr, nullptr};
    static cudaEvent_t evF = nullptr, evJ[TT] = {nullptr, nullptr};
    static bool attrSet = false;
    if (!sB2[0]) {
        cudaStreamCreateWithFlags(&sB2[0], cudaStreamNonBlocking);
        cudaStreamCreateWithFlags(&sB2[1], cudaStreamNonBlocking);
        cudaEventCreateWithFlags(&evF, cudaEventDisableTiming);
        cudaEventCreateWithFlags(&evJ[0], cudaEventDisableTiming);
        cudaEventCreateWithFlags(&evJ[1], cudaEventDisableTiming);
    }
    if (!attrSet) {
        cudaFuncSetAttribute(k_knn_tc, cudaFuncAttributeMaxDynamicSharedMemorySize, KNNT_SMEM);
        attrSet = true;
    }

    float *p_x0;
    double* p_stats;
    cudaGetSymbolAddress((void**)&p_x0, d_x0);
    cudaGetSymbolAddress((void**)&p_stats, d_stats);

    BranchPtrs bp[TT];
    {
        float *base;
        cudaGetSymbolAddress((void**)&base, d_hpre);
        for (int t = 0; t < TT; t++) bp[t].hpre = base + (size_t)t*M1*CCH;
        cudaGetSymbolAddress((void**)&base, d_h);
        for (int t = 0; t < TT; t++) bp[t].h = base + (size_t)t*M1*CCH;
        cudaGetSymbolAddress((void**)&base, d_xn);
        for (int t = 0; t < TT; t++) bp[t].xn = base + (size_t)t*M1*CCH;
        cudaGetSymbolAddress((void**)&base, d_sqv);
        for (int t = 0; t < TT; t++) bp[t].sqv = base + (size_t)t*M1;
        cudaGetSymbolAddress((void**)&base, d_u);
        for (int t = 0; t < TT; t++) bp[t].u = base + (size_t)t*M1*CH2;
        cudaGetSymbolAddress((void**)&base, d_v);
        for (int t = 0; t < TT; t++) bp[t].v = base + (size_t)t*M1*CH2;
        cudaGetSymbolAddress((void**)&base, d_xmax);
        for (int t = 0; t < TT; t++) bp[t].xmax = base + (size_t)t*M1*CH2;
        cudaGetSymbolAddress((void**)&base, d_xmin);
        for (int t = 0; t < TT; t++) bp[t].xmin = base + (size_t)t*M1*CH2;
        cudaGetSymbolAddress((void**)&base, d_pre2);
        for (int t = 0; t < TT; t++) bp[t].pre2 = base + (size_t)t*M1*CCH;
        cudaGetSymbolAddress((void**)&base, d_res);
        for (int t = 0; t < TT; t++) bp[t].res = base + (size_t)t*M1*CCH;
        cudaGetSymbolAddress((void**)&base, d_pref1);
        for (int t = 0; t < TT; t++) bp[t].pref1 = base + (size_t)t*M1*CH4;
        cudaGetSymbolAddress((void**)&base, d_pref2);
        for (int t = 0; t < TT; t++) bp[t].pref2 = base + (size_t)t*M1*CCH;
        __nv_bfloat16* hb;
        cudaGetSymbolAddress((void**)&hb, d_xnh);
        for (int t = 0; t < TT; t++) bp[t].xnh = hb + (size_t)t*M1*CCH;
        cudaGetSymbolAddress((void**)&hb, d_xnl);
        for (int t = 0; t < TT; t++) bp[t].xnl = hb + (size_t)t*M1*CCH;
        int* ibase;
        cudaGetSymbolAddress((void**)&ibase, d_idx);
        for (int t = 0; t < TT; t++) bp[t].idx = ibase + (size_t)t*M1*KK;
    }

    k_zero_stats_all<<<1, 512>>>();
    k_transpose_in<<<dim3(NN/32, CCH/32, BB), dim3(32, 8)>>>(x, p_x0);

    cudaEventRecord(evF, 0);
    cudaStreamWaitEvent(sB2[0], evF, 0);
    cudaStreamWaitEvent(sB2[1], evF, 0);

    for (int t = 0; t < TT; t++) {
        cudaStream_t st = sB2[t];
        BranchPtrs& p = bp[t];
        double* s_bn1  = p_stats + (t*5 + 0)*512;
        double* s_bng  = p_stats + (t*5 + 1)*512;
        double* s_bn2  = p_stats + (t*5 + 2)*512;
        double* s_bnf1 = p_stats + (t*5 + 3)*512;
        double* s_bnf2 = p_stats + (t*5 + 4)*512;

        k_gemm<0><<<dim3(1, M1/64), 256, 0, st>>>(
            p_x0, nullptr, W1 + (size_t)t*CCH*CCH, b1 + t*CCH,
            p.hpre, s_bn1, CCH, CCH, nullptr, nullptr, nullptr, 1, nullptr);
        k_apply_norm<<<M1/8, 256, 0, st>>>(p.hpre, p.h, p.xn, p.xnh, p.xnl, p.sqv,
                                           g1 + t*CCH, bt1 + t*CCH, s_bn1);
        k_knn_tc<<<BB*(NN/64), 256, KNNT_SMEM, st>>>(p.xn, p.xnh, p.xnl, p.sqv, p.idx);
        k_uv<<<dim3(1, M1/128, 2), 256, 0, st>>>(p.h, Wg + (size_t)t*CH2*CH2, p.u, p.v);
        k_gather<<<M1/32, 256, 0, st>>>(p.u, p.v, p.idx, bg + t*CH2,
                                        p.xmax, p.xmin, s_bng);
        k_gemm<1><<<dim3(1, M1/64), 256, 0, st>>>(
            p.xmax, p.xmin, W2 + (size_t)t*CH2*CCH, b2 + t*CCH,
            p.pre2, s_bn2, CH2, CCH, s_bng, gg + t*CH2, btg + t*CH2, MG, nullptr);
        k_gemm<3><<<dim3(CH4/64, M1/64), 256, 0, st>>>(
            p.pre2, p_x0, Wf1 + (size_t)t*CCH*CH4, bf1 + t*CH4,
            p.pref1, s_bnf1, CCH, CH4, s_bn2, g2 + t*CCH, bt2 + t*CCH, M1, p.res);
        k_gemm<2><<<dim3(1, M1/64), 256, 0, st>>>(
            p.pref1, nullptr, Wf2 + (size_t)t*CH4*CCH, bf2 + t*CCH,
            p.pref2, s_bnf2, CH4, CCH, s_bnf1, gf1 + t*CH4, btf1 + t*CH4, M1, nullptr);
        cudaEventRecord(evJ[t], st);
    }

    cudaStreamWaitEvent(0, evJ[0], 0);
    cudaStreamWaitEvent(0, evJ[1], 0);

    k_final<<<dim3(NN/32, CCH/32, BB), dim3(32, 8)>>>(alpha, bp[0].pref2, bp[0].res,
                                                      gf2, btf2, p_stats, out);
}